// round 11
// baseline (speedup 1.0000x reference)
#include <cuda_runtime.h>
#include <cstdint>
#include <cstddef>

typedef unsigned long long ull;

#define GDIM 64
#define G3 (GDIM*GDIM*GDIM)
#define BATCH 4
#define NPTS 200000
#define MAXPV 35.0f
#define MAXOCC 800000
#define NGEMM (MAXOCC/128)     // 6250
#define NTILES 8192

// ---------------- scratch ----------------
__device__ __align__(16) float g_accum[BATCH*G3*8];
__device__ float g_mm2[BATCH*64*6];
__device__ float g_A1t[7*64];
__device__ float g_c1[64];
__device__ __align__(16) float g_A2[64*128];
__device__ float g_c2[128];
__device__ unsigned g_nocc;
__device__ __align__(16) int   g_index[BATCH*G3];
__device__ __align__(16) float g_feat[(size_t)MAXOCC*8 + 1024];
__device__ __align__(16) float g_comp[(size_t)MAXOCC*128 + 1024];

// ---------------- helpers ----------------
__device__ __forceinline__ void upk2(ull v, float& lo, float& hi){
    asm("mov.b64 {%0, %1}, %2;" : "=f"(lo), "=f"(hi) : "l"(v));
}
__device__ __forceinline__ void ffma2(ull& acc, ull x, ull y){
    asm("fma.rn.f32x2 %0, %1, %2, %0;" : "+l"(acc) : "l"(x), "l"(y));
}
__device__ __forceinline__ void lds2x64(ull& a, ull& b, unsigned addr){
    asm volatile("ld.shared.v2.b64 {%0, %1}, [%2];" : "=l"(a), "=l"(b) : "r"(addr));
}
__device__ __forceinline__ void red4(float* addr, float x, float y, float z, float w){
    asm volatile("red.global.add.v4.f32 [%0], {%1,%2,%3,%4};"
                 :: "l"(addr), "f"(x), "f"(y), "f"(z), "f"(w) : "memory");
}

// ---------------- kernel 1: prep ----------------
__global__ void k_prep(const float* __restrict__ W1, const float* __restrict__ b1,
                       const float* __restrict__ g1, const float* __restrict__ be1,
                       const float* __restrict__ rm1, const float* __restrict__ rv1,
                       const float* __restrict__ W2, const float* __restrict__ b2,
                       const float* __restrict__ g2, const float* __restrict__ be2,
                       const float* __restrict__ rm2, const float* __restrict__ rv2,
                       const float* __restrict__ pc){
    if(blockIdx.x < 8192){
        int i = blockIdx.x*256 + threadIdx.x;
        ((float4*)g_accum)[i] = make_float4(0.f,0.f,0.f,0.f);
        if(blockIdx.x == 0){
            int t = threadIdx.x;
            if(t == 0) g_nocc = 0u;
            if(t < 64){
                float s = g1[t] / sqrtf(rv1[t] + 1e-5f);
                g_c1[t] = (b1[t] - rm1[t]) * s + be1[t];
                #pragma unroll
                for(int k = 0; k < 7; k++) g_A1t[k*64 + t] = W1[t*7 + k] * s;
            }
            if(t < 128){
                float s = g2[t] / sqrtf(rv2[t] + 1e-5f);
                g_c2[t] = (b2[t] - rm2[t]) * s + be2[t];
                for(int k = 0; k < 64; k++) g_A2[k*128 + t] = W2[t*64 + k] * s;
            }
        }
        return;
    }
    int m = blockIdx.x - 8192;
    int b = m >> 6, mloc = m & 63;
    const float* px = pc + b*6*NPTS;
    float mn0= 3.4e38f, mn1= 3.4e38f, mn2= 3.4e38f;
    float mx0=-3.4e38f, mx1=-3.4e38f, mx2=-3.4e38f;
    for(int n = mloc*256 + threadIdx.x; n < NPTS; n += 64*256){
        float x = px[n], y = px[NPTS+n], z = px[2*NPTS+n];
        mn0 = fminf(mn0,x); mx0 = fmaxf(mx0,x);
        mn1 = fminf(mn1,y); mx1 = fmaxf(mx1,y);
        mn2 = fminf(mn2,z); mx2 = fmaxf(mx2,z);
    }
    #pragma unroll
    for(int s = 16; s; s >>= 1){
        mn0 = fminf(mn0, __shfl_xor_sync(~0u, mn0, s));
        mn1 = fminf(mn1, __shfl_xor_sync(~0u, mn1, s));
        mn2 = fminf(mn2, __shfl_xor_sync(~0u, mn2, s));
        mx0 = fmaxf(mx0, __shfl_xor_sync(~0u, mx0, s));
        mx1 = fmaxf(mx1, __shfl_xor_sync(~0u, mx1, s));
        mx2 = fmaxf(mx2, __shfl_xor_sync(~0u, mx2, s));
    }
    __shared__ float wred[8][6];
    int wid = threadIdx.x >> 5;
    if((threadIdx.x & 31) == 0){
        wred[wid][0]=mn0; wred[wid][1]=mn1; wred[wid][2]=mn2;
        wred[wid][3]=mx0; wred[wid][4]=mx1; wred[wid][5]=mx2;
    }
    __syncthreads();
    if(threadIdx.x < 6){
        int c = threadIdx.x;
        bool isMin = c < 3;
        float acc = wred[0][c];
        #pragma unroll
        for(int w = 1; w < 8; w++) acc = isMin ? fminf(acc, wred[w][c]) : fmaxf(acc, wred[w][c]);
        g_mm2[m*6 + c] = acc;
    }
}

// ---------------- kernel 2: voxel scatter ----------------
__global__ void k_voxel(const float* __restrict__ pc){
    int b = blockIdx.y;
    __shared__ float red[6];
    {
        int wid = threadIdx.x >> 5, lid = threadIdx.x & 31;
        if(wid < 6){
            bool isMin = wid < 3;
            float acc = isMin ? 3.4e38f : -3.4e38f;
            for(int m = lid; m < 64; m += 32){
                float v = g_mm2[(b*64 + m)*6 + wid];
                acc = isMin ? fminf(acc, v) : fmaxf(acc, v);
            }
            #pragma unroll
            for(int s = 16; s; s >>= 1){
                float o = __shfl_xor_sync(~0u, acc, s);
                acc = isMin ? fminf(acc, o) : fmaxf(acc, o);
            }
            if(lid == 0) red[wid] = acc;
        }
        __syncthreads();
    }
    float mn0 = red[0], mn1 = red[1], mn2 = red[2];
    float d0 = red[3] - mn0 + 1e-7f;
    float d1 = red[4] - mn1 + 1e-7f;
    float d2 = red[5] - mn2 + 1e-7f;

    const float* p = pc + b*6*NPTS;
    float* acc = g_accum + (size_t)b*G3*8;
    for(int n = blockIdx.x*blockDim.x + threadIdx.x; n < NPTS; n += gridDim.x*blockDim.x){
        float x = p[n], y = p[NPTS+n], z = p[2*NPTS+n];
        float r = p[3*NPTS+n], g = p[4*NPTS+n], bl = p[5*NPTS+n];
        float tx = __fmul_rn(__fdiv_rn(x - mn0, d0), 63.0f);
        float ty = __fmul_rn(__fdiv_rn(y - mn1, d1), 63.0f);
        float tz = __fmul_rn(__fdiv_rn(z - mn2, d2), 63.0f);
        tx = fminf(fmaxf(tx, 0.0f), 62.9999f);
        ty = fminf(fmaxf(ty, 0.0f), 62.9999f);
        tz = fminf(fmaxf(tz, 0.0f), 62.9999f);
        int flat = (((int)tx)*GDIM + (int)ty)*GDIM + (int)tz;
        float* v = acc + (size_t)flat*8;
        red4(v,     x, y, z, 1.0f);
        red4(v + 4, r, g, bl, 0.0f);
    }
}

// ---------------- kernel 3: compaction ----------------
__global__ void k_compact(){
    int t = blockIdx.x*256 + threadIdx.x;
    int gv0 = t*4;
    unsigned lane = threadIdx.x & 31;

    float4 p0[4];
    #pragma unroll
    for(int v = 0; v < 4; v++) p0[v] = *(const float4*)(g_accum + (size_t)(gv0+v)*8);

    int cnt = 0;
    #pragma unroll
    for(int v = 0; v < 4; v++) cnt += (p0[v].w > 0.f);

    int x = cnt;
    #pragma unroll
    for(int d = 1; d < 32; d <<= 1){
        int y = __shfl_up_sync(0xFFFFFFFFu, x, d);
        if(lane >= d) x += y;
    }
    int excl = x - cnt;
    int total = __shfl_sync(0xFFFFFFFFu, x, 31);
    unsigned base = 0;
    if(lane == 31 && total) base = atomicAdd(&g_nocc, (unsigned)total);
    base = __shfl_sync(0xFFFFFFFFu, base, 31);

    int pos = (int)base + excl;
    int4 idx;
    int* ip = (int*)&idx;
    #pragma unroll
    for(int v = 0; v < 4; v++){
        if(p0[v].w > 0.f){
            ip[v] = pos;
            float4 p1 = *(const float4*)(g_accum + (size_t)(gv0+v)*8 + 4);
            float cntv = p0[v].w, dn = fmaxf(cntv, 1.0f);
            float* f = g_feat + (size_t)pos*8;
            f[0] = __fdiv_rn(p0[v].x, dn);
            f[1] = __fdiv_rn(p0[v].y, dn);
            f[2] = __fdiv_rn(p0[v].z, dn);
            f[3] = __fdiv_rn(fminf(cntv, MAXPV), MAXPV);
            f[4] = __fdiv_rn(p1.x, dn);
            f[5] = __fdiv_rn(p1.y, dn);
            f[6] = __fdiv_rn(p1.z, dn);
            f[7] = 0.f;
            pos++;
        } else {
            ip[v] = -1;
        }
    }
    *(int4*)(g_index + gv0) = idx;
}

// ---------------- kernel 4: dense MLP + interleaved empty-tile zero fill ----------------
#define SG_A2    0
#define SG_H     8192
#define SG_FEAT  24576
#define SG_A1    25600
#define SG_C1    26112
#define SG_C2    26176
#define SG_FLOATS 26304   // 105216 bytes

__device__ __forceinline__ void l2_full(unsigned aAddr, unsigned hAddr, ull (&a)[8][4]){
    #pragma unroll 4
    for(int k = 0; k < 64; k += 2){
        ull w00,w01,w02,w03, w10,w11,w12,w13;
        lds2x64(w00, w01, aAddr + (unsigned)k*512);
        lds2x64(w02, w03, aAddr + (unsigned)k*512 + 16);
        lds2x64(w10, w11, aAddr + (unsigned)k*512 + 512);
        lds2x64(w12, w13, aAddr + (unsigned)k*512 + 528);
        #pragma unroll
        for(int ch = 0; ch < 8; ch++){
            ull h0, h1;
            lds2x64(h0, h1, hAddr + (unsigned)ch*8192 + (unsigned)k*8);
            ffma2(a[ch][0], h0, w00);
            ffma2(a[ch][1], h0, w01);
            ffma2(a[ch][2], h0, w02);
            ffma2(a[ch][3], h0, w03);
            ffma2(a[ch][0], h1, w10);
            ffma2(a[ch][1], h1, w11);
            ffma2(a[ch][2], h1, w12);
            ffma2(a[ch][3], h1, w13);
        }
    }
}

__global__ void __launch_bounds__(256, 2) k_gemm(float* __restrict__ out){
    extern __shared__ float sm[];
    int tid = threadIdx.x;
    int bid = blockIdx.x;

    // role interleave: blocks [0,12500): even=gemm(bid/2), odd=fill(bid/2);
    // blocks [12500,14442): fill(6250 + bid - 12500)
    int role, idx;
    if(bid < 2*NGEMM){ role = bid & 1; idx = bid >> 1; }
    else { role = 1; idx = NGEMM + (bid - 2*NGEMM); }

    if(role == 1){
        // ---- empty-tile zero fill (no dependency on gemm output) ----
        int* idxS = (int*)sm;
        int b = idx >> 11;
        int vbase = (idx & 2047) << 7;
        if(tid < 128) idxS[tid] = g_index[b*G3 + vbase + tid];
        int any = __syncthreads_or(tid < 128 && idxS[tid] >= 0);
        if(any) return;
        float* ob = out + (size_t)b*128*G3 + vbase;
        float4 z4 = make_float4(0.f,0.f,0.f,0.f);
        for(int i = tid; i < 4096; i += 256){
            int c = i >> 5, q = i & 31;
            __stcs((float4*)(ob + (size_t)c*G3) + q, z4);
        }
        return;
    }

    // ---- gemm role ----
    int N = (int)g_nocc;
    int base = idx << 7;
    if(base >= N) return;

    float* A2S   = sm + SG_A2;
    float* featS = sm + SG_FEAT;
    float* A1tS  = sm + SG_A1;
    float* c1S   = sm + SG_C1;
    float* c2S   = sm + SG_C2;
    int cg = tid & 15, vg = tid >> 4;
    int c0 = cg*8;
    unsigned smemBase = (unsigned)__cvta_generic_to_shared(sm);
    unsigned hAddr = smemBase + SG_H*4 + (unsigned)vg*512;
    unsigned aAddr = smemBase + SG_A2*4 + (unsigned)c0*4;

    for(int i = tid; i < 512; i += 256)
        ((float2*)featS)[i] = ((const float2*)(g_feat + (size_t)base*8))[i];
    for(int i = tid; i < 448;  i += 256) A1tS[i] = g_A1t[i];
    if(tid < 64)  c1S[tid] = g_c1[tid];
    if(tid < 128) c2S[tid] = g_c2[tid];
    for(int i = tid; i < 2048; i += 256) ((float4*)A2S)[i] = ((const float4*)g_A2)[i];
    __syncthreads();

    float2* hS2 = (float2*)(sm + SG_H);
    for(int i = tid; i < 8192; i += 256){
        int slot = i >> 6, j = i & 63;
        float s = c1S[j];
        const float* f = featS + slot*8;
        #pragma unroll
        for(int k = 0; k < 7; k++) s = fmaf(f[k], A1tS[k*64+j], s);
        float h = fmaxf(s, 0.f);
        hS2[slot*64 + j] = make_float2(h, h);
    }
    __syncthreads();

    ull a[8][4];
    #pragma unroll
    for(int ch = 0; ch < 8; ch++)
        #pragma unroll
        for(int p = 0; p < 4; p++) a[ch][p] = 0ull;
    l2_full(aAddr, hAddr, a);

    #pragma unroll
    for(int ch = 0; ch < 8; ch++){
        int slot = ch*16 + vg;
        float o[8];
        #pragma unroll
        for(int p = 0; p < 4; p++){
            float lo, hi;
            upk2(a[ch][p], lo, hi);
            o[2*p  ] = fmaxf(lo + c2S[c0+2*p  ], 0.f);
            o[2*p+1] = fmaxf(hi + c2S[c0+2*p+1], 0.f);
        }
        float* dst = g_comp + (size_t)(base + slot)*128 + c0;
        *(float4*)(dst)     = make_float4(o[0], o[1], o[2], o[3]);
        *(float4*)(dst + 4) = make_float4(o[4], o[5], o[6], o[7]);
    }
}

// ---------------- kernel 5: bandwidth fill (non-empty tiles only) ----------------
#define SF_O     0
#define SF_IDX   16384
#define SF_FLOATS 16512

__global__ void __launch_bounds__(256, 3) k_fill(float* __restrict__ out){
    extern __shared__ float sm[];
    float* oS = sm + SF_O;
    int* idxS = (int*)(sm + SF_IDX);

    int tid = threadIdx.x;
    int t = blockIdx.x;
    int b = t >> 11;
    int vbase = (t & 2047) << 7;
    if(tid < 128) idxS[tid] = g_index[b*G3 + vbase + tid];
    int any = __syncthreads_or(tid < 128 && idxS[tid] >= 0);
    if(!any) return;                      // zero-fill already done in k_gemm launch

    float* ob = out + (size_t)b*128*G3 + vbase;
    float4 z4 = make_float4(0.f,0.f,0.f,0.f);

    for(int i = tid; i < 4096; i += 256) ((float4*)oS)[i] = z4;
    __syncthreads();

    int cg = tid & 15, vg = tid >> 4;
    int c0 = cg*8;
    #pragma unroll
    for(int vi = 0; vi < 8; vi++){
        int v = vg*8 + vi;
        int ix = idxS[v];
        if(ix >= 0){
            const float* src = g_comp + (size_t)ix*128 + c0;
            float4 r0 = __ldg((const float4*)src);
            float4 r1 = __ldg((const float4*)(src + 4));
            int basei = (((v >> 2) ^ cg) << 2) + (v & 3);
            oS[(c0+0)*128 + basei] = r0.x;
            oS[(c0+1)*128 + basei] = r0.y;
            oS[(c0+2)*128 + basei] = r0.z;
            oS[(c0+3)*128 + basei] = r0.w;
            oS[(c0+4)*128 + basei] = r1.x;
            oS[(c0+5)*128 + basei] = r1.y;
            oS[(c0+6)*128 + basei] = r1.z;
            oS[(c0+7)*128 + basei] = r1.w;
        }
    }
    __syncthreads();

    for(int i = tid; i < 4096; i += 256){
        int c = i >> 5, vq = i & 31;
        int s = (c >> 3) & 15;
        float4 v = *(const float4*)(oS + c*128 + ((vq ^ s) << 2));
        __stcs((float4*)(ob + (size_t)c*G3) + vq, v);
    }
}

// ---------------- launch ----------------
extern "C" void kernel_launch(void* const* d_in, const int* in_sizes, int n_in,
                              void* d_out, int out_size){
    const float* pc  = (const float*)d_in[0];
    const float* W1  = (const float*)d_in[1];
    const float* b1  = (const float*)d_in[2];
    const float* g1  = (const float*)d_in[3];
    const float* be1 = (const float*)d_in[4];
    const float* rm1 = (const float*)d_in[5];
    const float* rv1 = (const float*)d_in[6];
    const float* W2  = (const float*)d_in[7];
    const float* b2  = (const float*)d_in[8];
    const float* g2  = (const float*)d_in[9];
    const float* be2 = (const float*)d_in[10];
    const float* rm2 = (const float*)d_in[11];
    const float* rv2 = (const float*)d_in[12];

    cudaFuncSetAttribute(k_gemm, cudaFuncAttributeMaxDynamicSharedMemorySize, SG_FLOATS*4);
    cudaFuncSetAttribute(k_fill, cudaFuncAttributeMaxDynamicSharedMemorySize, SF_FLOATS*4);

    k_prep<<<8448, 256>>>(W1,b1,g1,be1,rm1,rv1,W2,b2,g2,be2,rm2,rv2, pc);
    k_voxel<<<dim3(782,4), 256>>>(pc);
    k_compact<<<1024, 256>>>();
    k_gemm<<<2*NGEMM + (NTILES - NGEMM), 256, SG_FLOATS*4>>>((float*)d_out);
    k_fill<<<BATCH*2048, 256, SF_FLOATS*4>>>((float*)d_out);
}

// round 12
// speedup vs baseline: 1.0971x; 1.0971x over previous
#include <cuda_runtime.h>
#include <cuda_bf16.h>
#include <cstdint>
#include <cstddef>

typedef unsigned long long ull;

#define GDIM 64
#define G3 (GDIM*GDIM*GDIM)
#define BATCH 4
#define NPTS 200000
#define MAXPV 35.0f
#define MAXOCC 800000
#define NGEMM (MAXOCC/128)

// ---------------- scratch ----------------
__device__ __align__(16) float g_accum[BATCH*G3*8];
__device__ float g_mm2[BATCH*64*6];
__device__ float g_A1t[7*64];
__device__ float g_c1[64];
__device__ float g_c2[128];
__device__ __align__(16) __nv_bfloat16 g_Whi[128*64];   // W2eff [c][k] bf16 hi
__device__ __align__(16) __nv_bfloat16 g_Wlo[128*64];   // bf16 residual
__device__ unsigned g_nocc;
__device__ __align__(16) int   g_index[BATCH*G3];
__device__ __align__(16) float g_feat[(size_t)MAXOCC*8 + 1024];
__device__ __align__(16) float g_comp[(size_t)MAXOCC*128 + 1024];

// ---------------- helpers ----------------
__device__ __forceinline__ void red4(float* addr, float x, float y, float z, float w){
    asm volatile("red.global.add.v4.f32 [%0], {%1,%2,%3,%4};"
                 :: "l"(addr), "f"(x), "f"(y), "f"(z), "f"(w) : "memory");
}
__device__ __forceinline__ void mma_bf16(float& c0, float& c1, float& c2, float& c3,
                                         uint32_t a0, uint32_t a1, uint32_t a2, uint32_t a3,
                                         uint32_t b0, uint32_t b1){
    asm volatile("mma.sync.aligned.m16n8k16.row.col.f32.bf16.bf16.f32 "
                 "{%0,%1,%2,%3}, {%4,%5,%6,%7}, {%8,%9}, {%0,%1,%2,%3};"
                 : "+f"(c0), "+f"(c1), "+f"(c2), "+f"(c3)
                 : "r"(a0), "r"(a1), "r"(a2), "r"(a3), "r"(b0), "r"(b1));
}

// ---------------- kernel 1: prep ----------------
__global__ void k_prep(const float* __restrict__ W1, const float* __restrict__ b1,
                       const float* __restrict__ g1, const float* __restrict__ be1,
                       const float* __restrict__ rm1, const float* __restrict__ rv1,
                       const float* __restrict__ W2, const float* __restrict__ b2,
                       const float* __restrict__ g2, const float* __restrict__ be2,
                       const float* __restrict__ rm2, const float* __restrict__ rv2,
                       const float* __restrict__ pc){
    if(blockIdx.x < 8192){
        int i = blockIdx.x*256 + threadIdx.x;
        ((float4*)g_accum)[i] = make_float4(0.f,0.f,0.f,0.f);
        if(blockIdx.x == 0){
            int t = threadIdx.x;
            if(t == 0) g_nocc = 0u;
            if(t < 64){
                float s = g1[t] / sqrtf(rv1[t] + 1e-5f);
                g_c1[t] = (b1[t] - rm1[t]) * s + be1[t];
                #pragma unroll
                for(int k = 0; k < 7; k++) g_A1t[k*64 + t] = W1[t*7 + k] * s;
            }
            if(t < 128){
                float s = g2[t] / sqrtf(rv2[t] + 1e-5f);
                g_c2[t] = (b2[t] - rm2[t]) * s + be2[t];
                for(int k = 0; k < 64; k++){
                    float w = W2[t*64 + k] * s;
                    __nv_bfloat16 hi = __float2bfloat16(w);
                    __nv_bfloat16 lo = __float2bfloat16(w - __bfloat162float(hi));
                    g_Whi[t*64 + k] = hi;
                    g_Wlo[t*64 + k] = lo;
                }
            }
        }
        return;
    }
    int m = blockIdx.x - 8192;
    int b = m >> 6, mloc = m & 63;
    const float* px = pc + b*6*NPTS;
    float mn0= 3.4e38f, mn1= 3.4e38f, mn2= 3.4e38f;
    float mx0=-3.4e38f, mx1=-3.4e38f, mx2=-3.4e38f;
    for(int n = mloc*256 + threadIdx.x; n < NPTS; n += 64*256){
        float x = px[n], y = px[NPTS+n], z = px[2*NPTS+n];
        mn0 = fminf(mn0,x); mx0 = fmaxf(mx0,x);
        mn1 = fminf(mn1,y); mx1 = fmaxf(mx1,y);
        mn2 = fminf(mn2,z); mx2 = fmaxf(mx2,z);
    }
    #pragma unroll
    for(int s = 16; s; s >>= 1){
        mn0 = fminf(mn0, __shfl_xor_sync(~0u, mn0, s));
        mn1 = fminf(mn1, __shfl_xor_sync(~0u, mn1, s));
        mn2 = fminf(mn2, __shfl_xor_sync(~0u, mn2, s));
        mx0 = fmaxf(mx0, __shfl_xor_sync(~0u, mx0, s));
        mx1 = fmaxf(mx1, __shfl_xor_sync(~0u, mx1, s));
        mx2 = fmaxf(mx2, __shfl_xor_sync(~0u, mx2, s));
    }
    __shared__ float wred[8][6];
    int wid = threadIdx.x >> 5;
    if((threadIdx.x & 31) == 0){
        wred[wid][0]=mn0; wred[wid][1]=mn1; wred[wid][2]=mn2;
        wred[wid][3]=mx0; wred[wid][4]=mx1; wred[wid][5]=mx2;
    }
    __syncthreads();
    if(threadIdx.x < 6){
        int c = threadIdx.x;
        bool isMin = c < 3;
        float acc = wred[0][c];
        #pragma unroll
        for(int w = 1; w < 8; w++) acc = isMin ? fminf(acc, wred[w][c]) : fmaxf(acc, wred[w][c]);
        g_mm2[m*6 + c] = acc;
    }
}

// ---------------- kernel 2: voxel scatter ----------------
__global__ void k_voxel(const float* __restrict__ pc){
    int b = blockIdx.y;
    __shared__ float red[6];
    {
        int wid = threadIdx.x >> 5, lid = threadIdx.x & 31;
        if(wid < 6){
            bool isMin = wid < 3;
            float acc = isMin ? 3.4e38f : -3.4e38f;
            for(int m = lid; m < 64; m += 32){
                float v = g_mm2[(b*64 + m)*6 + wid];
                acc = isMin ? fminf(acc, v) : fmaxf(acc, v);
            }
            #pragma unroll
            for(int s = 16; s; s >>= 1){
                float o = __shfl_xor_sync(~0u, acc, s);
                acc = isMin ? fminf(acc, o) : fmaxf(acc, o);
            }
            if(lid == 0) red[wid] = acc;
        }
        __syncthreads();
    }
    float mn0 = red[0], mn1 = red[1], mn2 = red[2];
    float d0 = red[3] - mn0 + 1e-7f;
    float d1 = red[4] - mn1 + 1e-7f;
    float d2 = red[5] - mn2 + 1e-7f;

    const float* p = pc + b*6*NPTS;
    float* acc = g_accum + (size_t)b*G3*8;
    for(int n = blockIdx.x*blockDim.x + threadIdx.x; n < NPTS; n += gridDim.x*blockDim.x){
        float x = p[n], y = p[NPTS+n], z = p[2*NPTS+n];
        float r = p[3*NPTS+n], g = p[4*NPTS+n], bl = p[5*NPTS+n];
        float tx = __fmul_rn(__fdiv_rn(x - mn0, d0), 63.0f);
        float ty = __fmul_rn(__fdiv_rn(y - mn1, d1), 63.0f);
        float tz = __fmul_rn(__fdiv_rn(z - mn2, d2), 63.0f);
        tx = fminf(fmaxf(tx, 0.0f), 62.9999f);
        ty = fminf(fmaxf(ty, 0.0f), 62.9999f);
        tz = fminf(fmaxf(tz, 0.0f), 62.9999f);
        int flat = (((int)tx)*GDIM + (int)ty)*GDIM + (int)tz;
        float* v = acc + (size_t)flat*8;
        red4(v,     x, y, z, 1.0f);
        red4(v + 4, r, g, bl, 0.0f);
    }
}

// ---------------- kernel 3: compaction ----------------
__global__ void k_compact(){
    int t = blockIdx.x*256 + threadIdx.x;
    int gv0 = t*4;
    unsigned lane = threadIdx.x & 31;

    float4 p0[4];
    #pragma unroll
    for(int v = 0; v < 4; v++) p0[v] = *(const float4*)(g_accum + (size_t)(gv0+v)*8);

    int cnt = 0;
    #pragma unroll
    for(int v = 0; v < 4; v++) cnt += (p0[v].w > 0.f);

    int x = cnt;
    #pragma unroll
    for(int d = 1; d < 32; d <<= 1){
        int y = __shfl_up_sync(0xFFFFFFFFu, x, d);
        if(lane >= d) x += y;
    }
    int excl = x - cnt;
    int total = __shfl_sync(0xFFFFFFFFu, x, 31);
    unsigned base = 0;
    if(lane == 31 && total) base = atomicAdd(&g_nocc, (unsigned)total);
    base = __shfl_sync(0xFFFFFFFFu, base, 31);

    int pos = (int)base + excl;
    int4 idx;
    int* ip = (int*)&idx;
    #pragma unroll
    for(int v = 0; v < 4; v++){
        if(p0[v].w > 0.f){
            ip[v] = pos;
            float4 p1 = *(const float4*)(g_accum + (size_t)(gv0+v)*8 + 4);
            float cntv = p0[v].w, dn = fmaxf(cntv, 1.0f);
            float* f = g_feat + (size_t)pos*8;
            f[0] = __fdiv_rn(p0[v].x, dn);
            f[1] = __fdiv_rn(p0[v].y, dn);
            f[2] = __fdiv_rn(p0[v].z, dn);
            f[3] = __fdiv_rn(fminf(cntv, MAXPV), MAXPV);
            f[4] = __fdiv_rn(p1.x, dn);
            f[5] = __fdiv_rn(p1.y, dn);
            f[6] = __fdiv_rn(p1.z, dn);
            f[7] = 0.f;
            pos++;
        } else {
            ip[v] = -1;
        }
    }
    *(int4*)(g_index + gv0) = idx;
}

// ---------------- kernel 4: HMMA MLP over compacted voxels ----------------
// padded row stride 72 bf16 (144B): word index 36*row + t -> banks 4g+t conflict-free
#define PSTR 72
#define SB_WHI  0                       // 128*72*2 = 18432
#define SB_WLO  18432
#define SB_HHI  36864
#define SB_HLO  55296
#define SB_FEAT 73728                   // 1024 floats
#define SB_A1T  77824                   // 448 floats
#define SB_C1   79616
#define SB_C2   79872
#define SB_BYTES 80384

__global__ void __launch_bounds__(256, 2) k_gemm(){
    extern __shared__ char smc[];
    int N = (int)g_nocc;
    int base = blockIdx.x << 7;
    if(base >= N) return;

    int tid = threadIdx.x;
    __nv_bfloat16* Whi = (__nv_bfloat16*)(smc + SB_WHI);
    __nv_bfloat16* Wlo = (__nv_bfloat16*)(smc + SB_WLO);
    __nv_bfloat16* Hhi = (__nv_bfloat16*)(smc + SB_HHI);
    __nv_bfloat16* Hlo = (__nv_bfloat16*)(smc + SB_HLO);
    float* featS = (float*)(smc + SB_FEAT);
    float* A1tS  = (float*)(smc + SB_A1T);
    float* c1S   = (float*)(smc + SB_C1);
    float* c2S   = (float*)(smc + SB_C2);

    // stage weights (padded rows) + feats + layer-1 consts
    for(int i = tid; i < 512; i += 256)
        ((float2*)featS)[i] = ((const float2*)(g_feat + (size_t)base*8))[i];
    for(int i = tid; i < 448; i += 256) A1tS[i] = g_A1t[i];
    if(tid < 64)  c1S[tid] = g_c1[tid];
    if(tid < 128) c2S[tid] = g_c2[tid];
    for(int i = tid; i < 4096; i += 256){
        int c = i >> 5, kp = (i & 31)*2;   // copy 2 bf16 at a time
        *(uint32_t*)(Whi + c*PSTR + kp) = *(const uint32_t*)(g_Whi + c*64 + kp);
        *(uint32_t*)(Wlo + c*PSTR + kp) = *(const uint32_t*)(g_Wlo + c*64 + kp);
    }
    __syncthreads();

    // layer 1: compute h fp32, split to bf16 hi/lo planes (padded rows)
    for(int i = tid; i < 4096; i += 256){
        int slot = i >> 5, jp = (i & 31)*2;
        float s0 = c1S[jp], s1 = c1S[jp+1];
        const float* f = featS + slot*8;
        #pragma unroll
        for(int k = 0; k < 7; k++){
            float fv = f[k];
            s0 = fmaf(fv, A1tS[k*64 + jp],   s0);
            s1 = fmaf(fv, A1tS[k*64 + jp+1], s1);
        }
        float h0 = fmaxf(s0, 0.f), h1 = fmaxf(s1, 0.f);
        __nv_bfloat16 h0h = __float2bfloat16(h0);
        __nv_bfloat16 h1h = __float2bfloat16(h1);
        __nv_bfloat16 h0l = __float2bfloat16(h0 - __bfloat162float(h0h));
        __nv_bfloat16 h1l = __float2bfloat16(h1 - __bfloat162float(h1h));
        uint32_t hiw = (uint32_t)*(uint16_t*)&h0h | ((uint32_t)*(uint16_t*)&h1h << 16);
        uint32_t low = (uint32_t)*(uint16_t*)&h0l | ((uint32_t)*(uint16_t*)&h1l << 16);
        *(uint32_t*)(Hhi + slot*PSTR + jp) = hiw;
        *(uint32_t*)(Hlo + slot*PSTR + jp) = low;
    }
    __syncthreads();

    // layer 2: per warp 16 slots x 128 channels via m16n8k16 HMMA, 3-pass bf16 split
    int w = tid >> 5, lane = tid & 31;
    int g = lane >> 2, t = lane & 3;
    int m0 = w*16;

    float acc[16][4];
    #pragma unroll
    for(int nt = 0; nt < 16; nt++)
        #pragma unroll
        for(int r = 0; r < 4; r++) acc[nt][r] = 0.f;

    const __nv_bfloat16* hArow = Hhi + (m0+g)*PSTR;      // hi plane row ptrs
    const __nv_bfloat16* hBrow = Hhi + (m0+g+8)*PSTR;
    const __nv_bfloat16* lArow = Hlo + (m0+g)*PSTR;
    const __nv_bfloat16* lBrow = Hlo + (m0+g+8)*PSTR;

    #pragma unroll
    for(int ks = 0; ks < 4; ks++){
        int kc = ks*16 + 2*t;
        uint32_t ah0 = *(const uint32_t*)(hArow + kc);
        uint32_t ah1 = *(const uint32_t*)(hBrow + kc);
        uint32_t ah2 = *(const uint32_t*)(hArow + kc + 8);
        uint32_t ah3 = *(const uint32_t*)(hBrow + kc + 8);
        uint32_t al0 = *(const uint32_t*)(lArow + kc);
        uint32_t al1 = *(const uint32_t*)(lBrow + kc);
        uint32_t al2 = *(const uint32_t*)(lArow + kc + 8);
        uint32_t al3 = *(const uint32_t*)(lBrow + kc + 8);
        #pragma unroll
        for(int nt = 0; nt < 16; nt++){
            int c = nt*8 + g;
            uint32_t bh0 = *(const uint32_t*)(Whi + c*PSTR + kc);
            uint32_t bh1 = *(const uint32_t*)(Whi + c*PSTR + kc + 8);
            uint32_t bl0 = *(const uint32_t*)(Wlo + c*PSTR + kc);
            uint32_t bl1 = *(const uint32_t*)(Wlo + c*PSTR + kc + 8);
            mma_bf16(acc[nt][0], acc[nt][1], acc[nt][2], acc[nt][3],
                     ah0, ah1, ah2, ah3, bh0, bh1);
            mma_bf16(acc[nt][0], acc[nt][1], acc[nt][2], acc[nt][3],
                     al0, al1, al2, al3, bh0, bh1);
            mma_bf16(acc[nt][0], acc[nt][1], acc[nt][2], acc[nt][3],
                     ah0, ah1, ah2, ah3, bl0, bl1);
        }
    }

    // epilogue: bias + relu, float2 stores to compact buffer
    int slotA = base + m0 + g;
    int slotB = slotA + 8;
    #pragma unroll
    for(int nt = 0; nt < 16; nt++){
        int ch = nt*8 + 2*t;
        float b0 = c2S[ch], b1 = c2S[ch+1];
        float2 vA = make_float2(fmaxf(acc[nt][0] + b0, 0.f), fmaxf(acc[nt][1] + b1, 0.f));
        float2 vB = make_float2(fmaxf(acc[nt][2] + b0, 0.f), fmaxf(acc[nt][3] + b1, 0.f));
        *(float2*)(g_comp + (size_t)slotA*128 + ch) = vA;
        *(float2*)(g_comp + (size_t)slotB*128 + ch) = vB;
    }
}

// ---------------- kernel 5: bandwidth fill ----------------
#define SF_O     0
#define SF_IDX   16384
#define SF_FLOATS 16512

__global__ void __launch_bounds__(256, 3) k_fill(float* __restrict__ out){
    extern __shared__ float sm[];
    float* oS = sm + SF_O;
    int* idxS = (int*)(sm + SF_IDX);

    int tid = threadIdx.x;
    int t = blockIdx.x;
    int b = t >> 11;
    int vbase = (t & 2047) << 7;
    if(tid < 128) idxS[tid] = g_index[b*G3 + vbase + tid];
    int any = __syncthreads_or(tid < 128 && idxS[tid] >= 0);

    float* ob = out + (size_t)b*128*G3 + vbase;
    float4 z4 = make_float4(0.f,0.f,0.f,0.f);
    if(!any){
        for(int i = tid; i < 4096; i += 256){
            int c = i >> 5, q = i & 31;
            __stcs((float4*)(ob + (size_t)c*G3) + q, z4);
        }
        return;
    }

    for(int i = tid; i < 4096; i += 256) ((float4*)oS)[i] = z4;
    __syncthreads();

    int cg = tid & 15, vg = tid >> 4;
    int c0 = cg*8;
    #pragma unroll
    for(int vi = 0; vi < 8; vi++){
        int v = vg*8 + vi;
        int ix = idxS[v];
        if(ix >= 0){
            const float* src = g_comp + (size_t)ix*128 + c0;
            float4 r0 = __ldg((const float4*)src);
            float4 r1 = __ldg((const float4*)(src + 4));
            int basei = (((v >> 2) ^ cg) << 2) + (v & 3);
            oS[(c0+0)*128 + basei] = r0.x;
            oS[(c0+1)*128 + basei] = r0.y;
            oS[(c0+2)*128 + basei] = r0.z;
            oS[(c0+3)*128 + basei] = r0.w;
            oS[(c0+4)*128 + basei] = r1.x;
            oS[(c0+5)*128 + basei] = r1.y;
            oS[(c0+6)*128 + basei] = r1.z;
            oS[(c0+7)*128 + basei] = r1.w;
        }
    }
    __syncthreads();

    for(int i = tid; i < 4096; i += 256){
        int c = i >> 5, vq = i & 31;
        int s = (c >> 3) & 15;
        float4 v = *(const float4*)(oS + c*128 + ((vq ^ s) << 2));
        __stcs((float4*)(ob + (size_t)c*G3) + vq, v);
    }
}

// ---------------- launch ----------------
extern "C" void kernel_launch(void* const* d_in, const int* in_sizes, int n_in,
                              void* d_out, int out_size){
    const float* pc  = (const float*)d_in[0];
    const float* W1  = (const float*)d_in[1];
    const float* b1  = (const float*)d_in[2];
    const float* g1  = (const float*)d_in[3];
    const float* be1 = (const float*)d_in[4];
    const float* rm1 = (const float*)d_in[5];
    const float* rv1 = (const float*)d_in[6];
    const float* W2  = (const float*)d_in[7];
    const float* b2  = (const float*)d_in[8];
    const float* g2  = (const float*)d_in[9];
    const float* be2 = (const float*)d_in[10];
    const float* rm2 = (const float*)d_in[11];
    const float* rv2 = (const float*)d_in[12];

    cudaFuncSetAttribute(k_gemm, cudaFuncAttributeMaxDynamicSharedMemorySize, SB_BYTES);
    cudaFuncSetAttribute(k_fill, cudaFuncAttributeMaxDynamicSharedMemorySize, SF_FLOATS*4);

    k_prep<<<8448, 256>>>(W1,b1,g1,be1,rm1,rv1,W2,b2,g2,be2,rm2,rv2, pc);
    k_voxel<<<dim3(782,4), 256>>>(pc);
    k_compact<<<1024, 256>>>();
    k_gemm<<<NGEMM, 256, SB_BYTES>>>();
    k_fill<<<BATCH*2048, 256, SF_FLOATS*4>>>((float*)d_out);
}

// round 13
// speedup vs baseline: 1.1390x; 1.0383x over previous
#include <cuda_runtime.h>
#include <cuda_bf16.h>
#include <cstdint>
#include <cstddef>

typedef unsigned long long ull;

#define GDIM 64
#define G3 (GDIM*GDIM*GDIM)
#define BATCH 4
#define NPTS 200000
#define MAXPV 35.0f
#define MAXOCC 800000
#define NGEMM (MAXOCC/128)

// ---------------- scratch ----------------
__device__ __align__(16) float g_accum[BATCH*G3*8];
__device__ float g_mm2[BATCH*64*6];
__device__ float g_A1t[7*64];
__device__ float g_c1[64];
__device__ float g_c2[128];
__device__ __align__(16) uint4 g_Wf[128*20];            // fragment-packed weights, stride 20 uint4/channel
__device__ unsigned g_nocc;
__device__ __align__(16) int   g_index[BATCH*G3];
__device__ __align__(16) float g_feat[(size_t)MAXOCC*8 + 1024];
__device__ __align__(16) float g_comp[(size_t)MAXOCC*128 + 1024];

// ---------------- helpers ----------------
__device__ __forceinline__ void red4(float* addr, float x, float y, float z, float w){
    asm volatile("red.global.add.v4.f32 [%0], {%1,%2,%3,%4};"
                 :: "l"(addr), "f"(x), "f"(y), "f"(z), "f"(w) : "memory");
}
__device__ __forceinline__ void mma_bf16(float& c0, float& c1, float& c2, float& c3,
                                         uint32_t a0, uint32_t a1, uint32_t a2, uint32_t a3,
                                         uint32_t b0, uint32_t b1){
    asm volatile("mma.sync.aligned.m16n8k16.row.col.f32.bf16.bf16.f32 "
                 "{%0,%1,%2,%3}, {%4,%5,%6,%7}, {%8,%9}, {%0,%1,%2,%3};"
                 : "+f"(c0), "+f"(c1), "+f"(c2), "+f"(c3)
                 : "r"(a0), "r"(a1), "r"(a2), "r"(a3), "r"(b0), "r"(b1));
}

// ---------------- kernel 1: prep ----------------
__global__ void k_prep(const float* __restrict__ W1, const float* __restrict__ b1,
                       const float* __restrict__ g1, const float* __restrict__ be1,
                       const float* __restrict__ rm1, const float* __restrict__ rv1,
                       const float* __restrict__ W2, const float* __restrict__ b2,
                       const float* __restrict__ g2, const float* __restrict__ be2,
                       const float* __restrict__ rm2, const float* __restrict__ rv2,
                       const float* __restrict__ pc){
    if(blockIdx.x < 8192){
        int i = blockIdx.x*256 + threadIdx.x;
        ((float4*)g_accum)[i] = make_float4(0.f,0.f,0.f,0.f);
        if(blockIdx.x == 0){
            int t = threadIdx.x;
            if(t == 0) g_nocc = 0u;
            if(t < 64){
                float s = g1[t] / sqrtf(rv1[t] + 1e-5f);
                g_c1[t] = (b1[t] - rm1[t]) * s + be1[t];
                #pragma unroll
                for(int k = 0; k < 7; k++) g_A1t[k*64 + t] = W1[t*7 + k] * s;
            }
            if(t < 128){
                float s = g2[t] / sqrtf(rv2[t] + 1e-5f);
                g_c2[t] = (b2[t] - rm2[t]) * s + be2[t];
                // fragment-packed hi/lo weight words
                uint32_t whi[32], wlo[32];
                for(int kw = 0; kw < 32; kw++){
                    float wa = W2[t*64 + 2*kw    ] * s;
                    float wb = W2[t*64 + 2*kw + 1] * s;
                    __nv_bfloat16 ha = __float2bfloat16(wa);
                    __nv_bfloat16 hb = __float2bfloat16(wb);
                    __nv_bfloat16 la = __float2bfloat16(wa - __bfloat162float(ha));
                    __nv_bfloat16 lb = __float2bfloat16(wb - __bfloat162float(hb));
                    whi[kw] = (uint32_t)*(uint16_t*)&ha | ((uint32_t)*(uint16_t*)&hb << 16);
                    wlo[kw] = (uint32_t)*(uint16_t*)&la | ((uint32_t)*(uint16_t*)&lb << 16);
                }
                for(int ks = 0; ks < 4; ks++)
                    for(int tt = 0; tt < 4; tt++){
                        int ws = ks*8 + tt;
                        uint4 f;
                        f.x = whi[ws]; f.y = whi[ws+4];
                        f.z = wlo[ws]; f.w = wlo[ws+4];
                        g_Wf[t*20 + ks*4 + tt] = f;
                    }
            }
        }
        return;
    }
    int m = blockIdx.x - 8192;
    int b = m >> 6, mloc = m & 63;
    const float* px = pc + b*6*NPTS;
    float mn0= 3.4e38f, mn1= 3.4e38f, mn2= 3.4e38f;
    float mx0=-3.4e38f, mx1=-3.4e38f, mx2=-3.4e38f;
    for(int n = mloc*256 + threadIdx.x; n < NPTS; n += 64*256){
        float x = px[n], y = px[NPTS+n], z = px[2*NPTS+n];
        mn0 = fminf(mn0,x); mx0 = fmaxf(mx0,x);
        mn1 = fminf(mn1,y); mx1 = fmaxf(mx1,y);
        mn2 = fminf(mn2,z); mx2 = fmaxf(mx2,z);
    }
    #pragma unroll
    for(int s = 16; s; s >>= 1){
        mn0 = fminf(mn0, __shfl_xor_sync(~0u, mn0, s));
        mn1 = fminf(mn1, __shfl_xor_sync(~0u, mn1, s));
        mn2 = fminf(mn2, __shfl_xor_sync(~0u, mn2, s));
        mx0 = fmaxf(mx0, __shfl_xor_sync(~0u, mx0, s));
        mx1 = fmaxf(mx1, __shfl_xor_sync(~0u, mx1, s));
        mx2 = fmaxf(mx2, __shfl_xor_sync(~0u, mx2, s));
    }
    __shared__ float wred[8][6];
    int wid = threadIdx.x >> 5;
    if((threadIdx.x & 31) == 0){
        wred[wid][0]=mn0; wred[wid][1]=mn1; wred[wid][2]=mn2;
        wred[wid][3]=mx0; wred[wid][4]=mx1; wred[wid][5]=mx2;
    }
    __syncthreads();
    if(threadIdx.x < 6){
        int c = threadIdx.x;
        bool isMin = c < 3;
        float acc = wred[0][c];
        #pragma unroll
        for(int w = 1; w < 8; w++) acc = isMin ? fminf(acc, wred[w][c]) : fmaxf(acc, wred[w][c]);
        g_mm2[m*6 + c] = acc;
    }
}

// ---------------- kernel 2: voxel scatter ----------------
__global__ void k_voxel(const float* __restrict__ pc){
    int b = blockIdx.y;
    __shared__ float red[6];
    {
        int wid = threadIdx.x >> 5, lid = threadIdx.x & 31;
        if(wid < 6){
            bool isMin = wid < 3;
            float acc = isMin ? 3.4e38f : -3.4e38f;
            for(int m = lid; m < 64; m += 32){
                float v = g_mm2[(b*64 + m)*6 + wid];
                acc = isMin ? fminf(acc, v) : fmaxf(acc, v);
            }
            #pragma unroll
            for(int s = 16; s; s >>= 1){
                float o = __shfl_xor_sync(~0u, acc, s);
                acc = isMin ? fminf(acc, o) : fmaxf(acc, o);
            }
            if(lid == 0) red[wid] = acc;
        }
        __syncthreads();
    }
    float mn0 = red[0], mn1 = red[1], mn2 = red[2];
    float d0 = red[3] - mn0 + 1e-7f;
    float d1 = red[4] - mn1 + 1e-7f;
    float d2 = red[5] - mn2 + 1e-7f;

    const float* p = pc + b*6*NPTS;
    float* acc = g_accum + (size_t)b*G3*8;
    for(int n = blockIdx.x*blockDim.x + threadIdx.x; n < NPTS; n += gridDim.x*blockDim.x){
        float x = p[n], y = p[NPTS+n], z = p[2*NPTS+n];
        float r = p[3*NPTS+n], g = p[4*NPTS+n], bl = p[5*NPTS+n];
        float tx = __fmul_rn(__fdiv_rn(x - mn0, d0), 63.0f);
        float ty = __fmul_rn(__fdiv_rn(y - mn1, d1), 63.0f);
        float tz = __fmul_rn(__fdiv_rn(z - mn2, d2), 63.0f);
        tx = fminf(fmaxf(tx, 0.0f), 62.9999f);
        ty = fminf(fmaxf(ty, 0.0f), 62.9999f);
        tz = fminf(fmaxf(tz, 0.0f), 62.9999f);
        int flat = (((int)tx)*GDIM + (int)ty)*GDIM + (int)tz;
        float* v = acc + (size_t)flat*8;
        red4(v,     x, y, z, 1.0f);
        red4(v + 4, r, g, bl, 0.0f);
    }
}

// ---------------- kernel 3: compaction ----------------
__global__ void k_compact(){
    int t = blockIdx.x*256 + threadIdx.x;
    int gv0 = t*4;
    unsigned lane = threadIdx.x & 31;

    float4 p0[4];
    #pragma unroll
    for(int v = 0; v < 4; v++) p0[v] = *(const float4*)(g_accum + (size_t)(gv0+v)*8);

    int cnt = 0;
    #pragma unroll
    for(int v = 0; v < 4; v++) cnt += (p0[v].w > 0.f);

    int x = cnt;
    #pragma unroll
    for(int d = 1; d < 32; d <<= 1){
        int y = __shfl_up_sync(0xFFFFFFFFu, x, d);
        if(lane >= d) x += y;
    }
    int excl = x - cnt;
    int total = __shfl_sync(0xFFFFFFFFu, x, 31);
    unsigned base = 0;
    if(lane == 31 && total) base = atomicAdd(&g_nocc, (unsigned)total);
    base = __shfl_sync(0xFFFFFFFFu, base, 31);

    int pos = (int)base + excl;
    int4 idx;
    int* ip = (int*)&idx;
    #pragma unroll
    for(int v = 0; v < 4; v++){
        if(p0[v].w > 0.f){
            ip[v] = pos;
            float4 p1 = *(const float4*)(g_accum + (size_t)(gv0+v)*8 + 4);
            float cntv = p0[v].w, dn = fmaxf(cntv, 1.0f);
            float* f = g_feat + (size_t)pos*8;
            f[0] = __fdiv_rn(p0[v].x, dn);
            f[1] = __fdiv_rn(p0[v].y, dn);
            f[2] = __fdiv_rn(p0[v].z, dn);
            f[3] = __fdiv_rn(fminf(cntv, MAXPV), MAXPV);
            f[4] = __fdiv_rn(p1.x, dn);
            f[5] = __fdiv_rn(p1.y, dn);
            f[6] = __fdiv_rn(p1.z, dn);
            f[7] = 0.f;
            pos++;
        } else {
            ip[v] = -1;
        }
    }
    *(int4*)(g_index + gv0) = idx;
}

// ---------------- kernel 4: HMMA MLP, fragment-packed weights ----------------
#define PSTR 72
#define SB_WF   0                        // 128*20 uint4 = 40960 B
#define SB_HHI  40960                    // 128*72*2 = 18432
#define SB_HLO  59392
#define SB_FEAT 77824                    // 1024 floats
#define SB_A1T  81920                    // 448 floats
#define SB_C1   83712
#define SB_C2   83968
#define SB_BYTES 84480

__global__ void __launch_bounds__(256, 2) k_gemm(){
    extern __shared__ char smc[];
    int N = (int)g_nocc;
    int base = blockIdx.x << 7;
    if(base >= N) return;

    int tid = threadIdx.x;
    uint4* Wfs = (uint4*)(smc + SB_WF);
    __nv_bfloat16* Hhi = (__nv_bfloat16*)(smc + SB_HHI);
    __nv_bfloat16* Hlo = (__nv_bfloat16*)(smc + SB_HLO);
    float* featS = (float*)(smc + SB_FEAT);
    float* A1tS  = (float*)(smc + SB_A1T);
    float* c1S   = (float*)(smc + SB_C1);
    float* c2S   = (float*)(smc + SB_C2);

    // stage: fragment weights (used slots only), feats, layer-1 consts
    for(int i = tid; i < 512; i += 256)
        ((float2*)featS)[i] = ((const float2*)(g_feat + (size_t)base*8))[i];
    for(int i = tid; i < 448; i += 256) A1tS[i] = g_A1t[i];
    if(tid < 64)  c1S[tid] = g_c1[tid];
    if(tid < 128) c2S[tid] = g_c2[tid];
    for(int i = tid; i < 2048; i += 256){
        int c = i >> 4, r = i & 15;
        Wfs[c*20 + r] = g_Wf[c*20 + r];
    }
    __syncthreads();

    // layer 1: compute h fp32, split to bf16 hi/lo planes (padded rows)
    for(int i = tid; i < 4096; i += 256){
        int slot = i >> 5, jp = (i & 31)*2;
        float s0 = c1S[jp], s1 = c1S[jp+1];
        const float* f = featS + slot*8;
        #pragma unroll
        for(int k = 0; k < 7; k++){
            float fv = f[k];
            s0 = fmaf(fv, A1tS[k*64 + jp],   s0);
            s1 = fmaf(fv, A1tS[k*64 + jp+1], s1);
        }
        float h0 = fmaxf(s0, 0.f), h1 = fmaxf(s1, 0.f);
        __nv_bfloat16 h0h = __float2bfloat16(h0);
        __nv_bfloat16 h1h = __float2bfloat16(h1);
        __nv_bfloat16 h0l = __float2bfloat16(h0 - __bfloat162float(h0h));
        __nv_bfloat16 h1l = __float2bfloat16(h1 - __bfloat162float(h1h));
        uint32_t hiw = (uint32_t)*(uint16_t*)&h0h | ((uint32_t)*(uint16_t*)&h1h << 16);
        uint32_t low = (uint32_t)*(uint16_t*)&h0l | ((uint32_t)*(uint16_t*)&h1l << 16);
        *(uint32_t*)(Hhi + slot*PSTR + jp) = hiw;
        *(uint32_t*)(Hlo + slot*PSTR + jp) = low;
    }
    __syncthreads();

    // layer 2: per warp 16 slots x 128 channels, 3-pass bf16 split HMMA
    int w = tid >> 5, lane = tid & 31;
    int g = lane >> 2, t = lane & 3;
    int m0 = w*16;

    float acc[16][4];
    #pragma unroll
    for(int nt = 0; nt < 16; nt++)
        #pragma unroll
        for(int r = 0; r < 4; r++) acc[nt][r] = 0.f;

    const __nv_bfloat16* hArow = Hhi + (m0+g)*PSTR;
    const __nv_bfloat16* hBrow = Hhi + (m0+g+8)*PSTR;
    const __nv_bfloat16* lArow = Hlo + (m0+g)*PSTR;
    const __nv_bfloat16* lBrow = Hlo + (m0+g+8)*PSTR;

    #pragma unroll
    for(int ks = 0; ks < 4; ks++){
        int kc = ks*16 + 2*t;
        uint32_t ah0 = *(const uint32_t*)(hArow + kc);
        uint32_t ah1 = *(const uint32_t*)(hBrow + kc);
        uint32_t ah2 = *(const uint32_t*)(hArow + kc + 8);
        uint32_t ah3 = *(const uint32_t*)(hBrow + kc + 8);
        uint32_t al0 = *(const uint32_t*)(lArow + kc);
        uint32_t al1 = *(const uint32_t*)(lBrow + kc);
        uint32_t al2 = *(const uint32_t*)(lArow + kc + 8);
        uint32_t al3 = *(const uint32_t*)(lBrow + kc + 8);
        #pragma unroll
        for(int nt = 0; nt < 16; nt++){
            uint4 wf = Wfs[(nt*8 + g)*20 + ks*4 + t];
            mma_bf16(acc[nt][0], acc[nt][1], acc[nt][2], acc[nt][3],
                     ah0, ah1, ah2, ah3, wf.x, wf.y);
            mma_bf16(acc[nt][0], acc[nt][1], acc[nt][2], acc[nt][3],
                     al0, al1, al2, al3, wf.x, wf.y);
            mma_bf16(acc[nt][0], acc[nt][1], acc[nt][2], acc[nt][3],
                     ah0, ah1, ah2, ah3, wf.z, wf.w);
        }
    }

    // epilogue: bias + relu, float2 stores to compact buffer
    int slotA = base + m0 + g;
    int slotB = slotA + 8;
    #pragma unroll
    for(int nt = 0; nt < 16; nt++){
        int ch = nt*8 + 2*t;
        float b0 = c2S[ch], b1 = c2S[ch+1];
        float2 vA = make_float2(fmaxf(acc[nt][0] + b0, 0.f), fmaxf(acc[nt][1] + b1, 0.f));
        float2 vB = make_float2(fmaxf(acc[nt][2] + b0, 0.f), fmaxf(acc[nt][3] + b1, 0.f));
        *(float2*)(g_comp + (size_t)slotA*128 + ch) = vA;
        *(float2*)(g_comp + (size_t)slotB*128 + ch) = vB;
    }
}

// ---------------- kernel 5: bandwidth fill ----------------
#define SF_O     0
#define SF_IDX   16384
#define SF_FLOATS 16512

__global__ void __launch_bounds__(256, 3) k_fill(float* __restrict__ out){
    extern __shared__ float sm[];
    float* oS = sm + SF_O;
    int* idxS = (int*)(sm + SF_IDX);

    int tid = threadIdx.x;
    int t = blockIdx.x;
    int b = t >> 11;
    int vbase = (t & 2047) << 7;
    if(tid < 128) idxS[tid] = g_index[b*G3 + vbase + tid];
    int any = __syncthreads_or(tid < 128 && idxS[tid] >= 0);

    float* ob = out + (size_t)b*128*G3 + vbase;
    float4 z4 = make_float4(0.f,0.f,0.f,0.f);
    if(!any){
        for(int i = tid; i < 4096; i += 256){
            int c = i >> 5, q = i & 31;
            __stcs((float4*)(ob + (size_t)c*G3) + q, z4);
        }
        return;
    }

    for(int i = tid; i < 4096; i += 256) ((float4*)oS)[i] = z4;
    __syncthreads();

    int cg = tid & 15, vg = tid >> 4;
    int c0 = cg*8;
    #pragma unroll
    for(int vi = 0; vi < 8; vi++){
        int v = vg*8 + vi;
        int ix = idxS[v];
        if(ix >= 0){
            const float* src = g_comp + (size_t)ix*128 + c0;
            float4 r0 = __ldg((const float4*)src);
            float4 r1 = __ldg((const float4*)(src + 4));
            int basei = (((v >> 2) ^ cg) << 2) + (v & 3);
            oS[(c0+0)*128 + basei] = r0.x;
            oS[(c0+1)*128 + basei] = r0.y;
            oS[(c0+2)*128 + basei] = r0.z;
            oS[(c0+3)*128 + basei] = r0.w;
            oS[(c0+4)*128 + basei] = r1.x;
            oS[(c0+5)*128 + basei] = r1.y;
            oS[(c0+6)*128 + basei] = r1.z;
            oS[(c0+7)*128 + basei] = r1.w;
        }
    }
    __syncthreads();

    for(int i = tid; i < 4096; i += 256){
        int c = i >> 5, vq = i & 31;
        int s = (c >> 3) & 15;
        float4 v = *(const float4*)(oS + c*128 + ((vq ^ s) << 2));
        __stcs((float4*)(ob + (size_t)c*G3) + vq, v);
    }
}

// ---------------- launch ----------------
extern "C" void kernel_launch(void* const* d_in, const int* in_sizes, int n_in,
                              void* d_out, int out_size){
    const float* pc  = (const float*)d_in[0];
    const float* W1  = (const float*)d_in[1];
    const float* b1  = (const float*)d_in[2];
    const float* g1  = (const float*)d_in[3];
    const float* be1 = (const float*)d_in[4];
    const float* rm1 = (const float*)d_in[5];
    const float* rv1 = (const float*)d_in[6];
    const float* W2  = (const float*)d_in[7];
    const float* b2  = (const float*)d_in[8];
    const float* g2  = (const float*)d_in[9];
    const float* be2 = (const float*)d_in[10];
    const float* rm2 = (const float*)d_in[11];
    const float* rv2 = (const float*)d_in[12];

    cudaFuncSetAttribute(k_gemm, cudaFuncAttributeMaxDynamicSharedMemorySize, SB_BYTES);
    cudaFuncSetAttribute(k_fill, cudaFuncAttributeMaxDynamicSharedMemorySize, SF_FLOATS*4);

    k_prep<<<8448, 256>>>(W1,b1,g1,be1,rm1,rv1,W2,b2,g2,be2,rm2,rv2, pc);
    k_voxel<<<dim3(782,4), 256>>>(pc);
    k_compact<<<1024, 256>>>();
    k_gemm<<<NGEMM, 256, SB_BYTES>>>();
    k_fill<<<BATCH*2048, 256, SF_FLOATS*4>>>((float*)d_out);
}

// round 14
// speedup vs baseline: 1.2393x; 1.0881x over previous
#include <cuda_runtime.h>
#include <cuda_bf16.h>
#include <cstdint>
#include <cstddef>

typedef unsigned long long ull;

#define GDIM 64
#define G3 (GDIM*GDIM*GDIM)
#define BATCH 4
#define NPTS 200000
#define MAXPV 35.0f
#define NTILES 8192
#define PSTR 72

// ---------------- scratch ----------------
__device__ __align__(16) float g_accum[BATCH*G3*8];
__device__ float g_mm2[BATCH*64*6];
__device__ float g_A1t[7*64];
__device__ float g_c1[64];
__device__ float g_c2[128];
__device__ __align__(16) uint4 g_Wf[128*20];   // fragment-packed hi/lo weights, stride 20 uint4/channel

// ---------------- helpers ----------------
__device__ __forceinline__ void red4(float* addr, float x, float y, float z, float w){
    asm volatile("red.global.add.v4.f32 [%0], {%1,%2,%3,%4};"
                 :: "l"(addr), "f"(x), "f"(y), "f"(z), "f"(w) : "memory");
}
__device__ __forceinline__ void mma_bf16(float& c0, float& c1, float& c2, float& c3,
                                         uint32_t a0, uint32_t a1, uint32_t a2, uint32_t a3,
                                         uint32_t b0, uint32_t b1){
    asm volatile("mma.sync.aligned.m16n8k16.row.col.f32.bf16.bf16.f32 "
                 "{%0,%1,%2,%3}, {%4,%5,%6,%7}, {%8,%9}, {%0,%1,%2,%3};"
                 : "+f"(c0), "+f"(c1), "+f"(c2), "+f"(c3)
                 : "r"(a0), "r"(a1), "r"(a2), "r"(a3), "r"(b0), "r"(b1));
}

// ---------------- kernel 1: prep ----------------
__global__ void k_prep(const float* __restrict__ W1, const float* __restrict__ b1,
                       const float* __restrict__ g1, const float* __restrict__ be1,
                       const float* __restrict__ rm1, const float* __restrict__ rv1,
                       const float* __restrict__ W2, const float* __restrict__ b2,
                       const float* __restrict__ g2, const float* __restrict__ be2,
                       const float* __restrict__ rm2, const float* __restrict__ rv2,
                       const float* __restrict__ pc){
    if(blockIdx.x < 8192){
        int i = blockIdx.x*256 + threadIdx.x;
        ((float4*)g_accum)[i] = make_float4(0.f,0.f,0.f,0.f);
        if(blockIdx.x == 0){
            int t = threadIdx.x;
            if(t < 64){
                float s = g1[t] / sqrtf(rv1[t] + 1e-5f);
                g_c1[t] = (b1[t] - rm1[t]) * s + be1[t];
                #pragma unroll
                for(int k = 0; k < 7; k++) g_A1t[k*64 + t] = W1[t*7 + k] * s;
            }
            if(t < 128){
                float s = g2[t] / sqrtf(rv2[t] + 1e-5f);
                g_c2[t] = (b2[t] - rm2[t]) * s + be2[t];
                uint32_t whi[32], wlo[32];
                for(int kw = 0; kw < 32; kw++){
                    float wa = W2[t*64 + 2*kw    ] * s;
                    float wb = W2[t*64 + 2*kw + 1] * s;
                    __nv_bfloat16 ha = __float2bfloat16(wa);
                    __nv_bfloat16 hb = __float2bfloat16(wb);
                    __nv_bfloat16 la = __float2bfloat16(wa - __bfloat162float(ha));
                    __nv_bfloat16 lb = __float2bfloat16(wb - __bfloat162float(hb));
                    whi[kw] = (uint32_t)*(uint16_t*)&ha | ((uint32_t)*(uint16_t*)&hb << 16);
                    wlo[kw] = (uint32_t)*(uint16_t*)&la | ((uint32_t)*(uint16_t*)&lb << 16);
                }
                for(int ks = 0; ks < 4; ks++)
                    for(int tt = 0; tt < 4; tt++){
                        int ws = ks*8 + tt;
                        uint4 f;
                        f.x = whi[ws]; f.y = whi[ws+4];
                        f.z = wlo[ws]; f.w = wlo[ws+4];
                        g_Wf[t*20 + ks*4 + tt] = f;
                    }
            }
        }
        return;
    }
    int m = blockIdx.x - 8192;
    int b = m >> 6, mloc = m & 63;
    const float* px = pc + b*6*NPTS;
    float mn0= 3.4e38f, mn1= 3.4e38f, mn2= 3.4e38f;
    float mx0=-3.4e38f, mx1=-3.4e38f, mx2=-3.4e38f;
    for(int n = mloc*256 + threadIdx.x; n < NPTS; n += 64*256){
        float x = px[n], y = px[NPTS+n], z = px[2*NPTS+n];
        mn0 = fminf(mn0,x); mx0 = fmaxf(mx0,x);
        mn1 = fminf(mn1,y); mx1 = fmaxf(mx1,y);
        mn2 = fminf(mn2,z); mx2 = fmaxf(mx2,z);
    }
    #pragma unroll
    for(int s = 16; s; s >>= 1){
        mn0 = fminf(mn0, __shfl_xor_sync(~0u, mn0, s));
        mn1 = fminf(mn1, __shfl_xor_sync(~0u, mn1, s));
        mn2 = fminf(mn2, __shfl_xor_sync(~0u, mn2, s));
        mx0 = fmaxf(mx0, __shfl_xor_sync(~0u, mx0, s));
        mx1 = fmaxf(mx1, __shfl_xor_sync(~0u, mx1, s));
        mx2 = fmaxf(mx2, __shfl_xor_sync(~0u, mx2, s));
    }
    __shared__ float wred[8][6];
    int wid = threadIdx.x >> 5;
    if((threadIdx.x & 31) == 0){
        wred[wid][0]=mn0; wred[wid][1]=mn1; wred[wid][2]=mn2;
        wred[wid][3]=mx0; wred[wid][4]=mx1; wred[wid][5]=mx2;
    }
    __syncthreads();
    if(threadIdx.x < 6){
        int c = threadIdx.x;
        bool isMin = c < 3;
        float acc = wred[0][c];
        #pragma unroll
        for(int w = 1; w < 8; w++) acc = isMin ? fminf(acc, wred[w][c]) : fmaxf(acc, wred[w][c]);
        g_mm2[m*6 + c] = acc;
    }
}

// ---------------- kernel 2: voxel scatter ----------------
__global__ void k_voxel(const float* __restrict__ pc){
    int b = blockIdx.y;
    __shared__ float red[6];
    {
        int wid = threadIdx.x >> 5, lid = threadIdx.x & 31;
        if(wid < 6){
            bool isMin = wid < 3;
            float acc = isMin ? 3.4e38f : -3.4e38f;
            for(int m = lid; m < 64; m += 32){
                float v = g_mm2[(b*64 + m)*6 + wid];
                acc = isMin ? fminf(acc, v) : fmaxf(acc, v);
            }
            #pragma unroll
            for(int s = 16; s; s >>= 1){
                float o = __shfl_xor_sync(~0u, acc, s);
                acc = isMin ? fminf(acc, o) : fmaxf(acc, o);
            }
            if(lid == 0) red[wid] = acc;
        }
        __syncthreads();
    }
    float mn0 = red[0], mn1 = red[1], mn2 = red[2];
    float d0 = red[3] - mn0 + 1e-7f;
    float d1 = red[4] - mn1 + 1e-7f;
    float d2 = red[5] - mn2 + 1e-7f;

    const float* p = pc + b*6*NPTS;
    float* acc = g_accum + (size_t)b*G3*8;
    for(int n = blockIdx.x*blockDim.x + threadIdx.x; n < NPTS; n += gridDim.x*blockDim.x){
        float x = p[n], y = p[NPTS+n], z = p[2*NPTS+n];
        float r = p[3*NPTS+n], g = p[4*NPTS+n], bl = p[5*NPTS+n];
        float tx = __fmul_rn(__fdiv_rn(x - mn0, d0), 63.0f);
        float ty = __fmul_rn(__fdiv_rn(y - mn1, d1), 63.0f);
        float tz = __fmul_rn(__fdiv_rn(z - mn2, d2), 63.0f);
        tx = fminf(fmaxf(tx, 0.0f), 62.9999f);
        ty = fminf(fmaxf(ty, 0.0f), 62.9999f);
        tz = fminf(fmaxf(tz, 0.0f), 62.9999f);
        int flat = (((int)tx)*GDIM + (int)ty)*GDIM + (int)tz;
        float* v = acc + (size_t)flat*8;
        red4(v,     x, y, z, 1.0f);
        red4(v + 4, r, g, bl, 0.0f);
    }
}

// ---------------- kernel 3: fused per-tile MLP + output store ----------------
// smem layout (bytes). oS (64KB floats at 0) OVERLAYS Wf+H regions — only used
// after the post-HMMA __syncthreads when both are dead.
#define SB_WF    0                       // 128*20 uint4 = 40960
#define SB_HHI   40960                   // 128*72*2 = 18432
#define SB_HLO   59392                   // +18432 = 77824
#define SB_FEAT  77824                   // 1024 floats -> 81920
#define SB_A1T   81920                   // 448 floats  -> 83712
#define SB_C1    83712                   // 64 f -> 83968
#define SB_C2    83968                   // 128 f -> 84480
#define SB_PERM  84480                   // 128 int -> 84992
#define SB_AUX   84992                   // -> 85056
#define SB_BYTES 85056

__global__ void __launch_bounds__(256, 2) k_tile(float* __restrict__ out){
    extern __shared__ char smc[];
    uint4* Wfs = (uint4*)(smc + SB_WF);
    __nv_bfloat16* Hhi = (__nv_bfloat16*)(smc + SB_HHI);
    __nv_bfloat16* Hlo = (__nv_bfloat16*)(smc + SB_HLO);
    float* featS = (float*)(smc + SB_FEAT);
    float* A1tS  = (float*)(smc + SB_A1T);
    float* c1S   = (float*)(smc + SB_C1);
    float* c2S   = (float*)(smc + SB_C2);
    int*   permS = (int*)(smc + SB_PERM);
    int*   auxS  = (int*)(smc + SB_AUX);
    float* oS    = (float*)smc;          // overlay

    int tid = threadIdx.x;
    int tile = blockIdx.x;
    int b = tile >> 11;
    int vbase = (tile & 2047) << 7;
    const float* acc = g_accum + ((size_t)b*G3 + vbase)*8;
    float* ob = out + (size_t)b*128*G3 + vbase;

    // phase 1: load accumulators, ballot occupancy
    float4 p0 = make_float4(0,0,0,0), p1 = make_float4(0,0,0,0);
    int occ = 0;
    if(tid < 128){
        p0 = *(const float4*)(acc + tid*8);
        p1 = *(const float4*)(acc + tid*8 + 4);
        occ = p0.w > 0.f;
    }
    unsigned bal = __ballot_sync(0xFFFFFFFFu, occ);
    if(tid < 128 && (tid & 31) == 0) auxS[tid >> 5] = __popc(bal);
    __syncthreads();
    int n0 = auxS[0], n1 = auxS[1], n2 = auxS[2], n3 = auxS[3];
    int M = n0 + n1 + n2 + n3;

    if(M == 0){
        float4 z4 = make_float4(0.f,0.f,0.f,0.f);
        for(int i = tid; i < 4096; i += 256){
            int c = i >> 5, q = i & 31;
            __stcs((float4*)(ob + (size_t)c*G3) + q, z4);
        }
        return;
    }

    // phase 2: features + perm + weight staging
    if(occ){
        float dn = fmaxf(p0.w, 1.0f);
        float* f = featS + tid*8;
        f[0] = __fdiv_rn(p0.x, dn);
        f[1] = __fdiv_rn(p0.y, dn);
        f[2] = __fdiv_rn(p0.z, dn);
        f[3] = __fdiv_rn(fminf(p0.w, MAXPV), MAXPV);
        f[4] = __fdiv_rn(p1.x, dn);
        f[5] = __fdiv_rn(p1.y, dn);
        f[6] = __fdiv_rn(p1.z, dn);
        f[7] = 0.f;
        int w = tid >> 5;
        int off = (w > 0 ? n0 : 0) + (w > 1 ? n1 : 0) + (w > 2 ? n2 : 0);
        permS[off + __popc(bal & ((1u << (tid & 31)) - 1u))] = tid;
    }
    for(int i = tid; i < 2048; i += 256){
        int c = i >> 4, r = i & 15;
        Wfs[c*20 + r] = g_Wf[c*20 + r];
    }
    for(int i = tid; i < 448; i += 256) A1tS[i] = g_A1t[i];
    if(tid < 64)  c1S[tid] = g_c1[tid];
    if(tid < 128) c2S[tid] = g_c2[tid];
    __syncthreads();

    // phase 3: layer 1 for occupied slots -> bf16 hi/lo planes (pads left stale; unused)
    for(int i = tid; i < M*32; i += 256){
        int slot = i >> 5, jp = (i & 31)*2;
        int v = permS[slot];
        float s0 = c1S[jp], s1 = c1S[jp+1];
        const float* f = featS + v*8;
        #pragma unroll
        for(int k = 0; k < 7; k++){
            float fv = f[k];
            s0 = fmaf(fv, A1tS[k*64 + jp],   s0);
            s1 = fmaf(fv, A1tS[k*64 + jp+1], s1);
        }
        float h0 = fmaxf(s0, 0.f), h1 = fmaxf(s1, 0.f);
        __nv_bfloat16 h0h = __float2bfloat16(h0);
        __nv_bfloat16 h1h = __float2bfloat16(h1);
        __nv_bfloat16 h0l = __float2bfloat16(h0 - __bfloat162float(h0h));
        __nv_bfloat16 h1l = __float2bfloat16(h1 - __bfloat162float(h1h));
        uint32_t hiw = (uint32_t)*(uint16_t*)&h0h | ((uint32_t)*(uint16_t*)&h1h << 16);
        uint32_t low = (uint32_t)*(uint16_t*)&h0l | ((uint32_t)*(uint16_t*)&h1l << 16);
        *(uint32_t*)(Hhi + slot*PSTR + jp) = hiw;
        *(uint32_t*)(Hlo + slot*PSTR + jp) = low;
    }
    __syncthreads();

    // phase 4: HMMA jobs. job j: chunk=j>>1 (16 slots), channel half=(j&1)*64.
    int nchunk = (M + 15) >> 4;
    int njobs = nchunk*2;
    int w = tid >> 5, lane = tid & 31;
    int g = lane >> 2, t = lane & 3;

    float accr[2][8][4];
    #pragma unroll
    for(int jj = 0; jj < 2; jj++)
        #pragma unroll
        for(int nt = 0; nt < 8; nt++)
            #pragma unroll
            for(int r = 0; r < 4; r++) accr[jj][nt][r] = 0.f;

    #pragma unroll
    for(int jj = 0; jj < 2; jj++){
        int j = w + jj*8;
        if(j < njobs){
            int chunk = j >> 1, cb = (j & 1)*64;
            int m0 = chunk*16;
            const __nv_bfloat16* hArow = Hhi + (m0+g)*PSTR;
            const __nv_bfloat16* hBrow = Hhi + (m0+g+8)*PSTR;
            const __nv_bfloat16* lArow = Hlo + (m0+g)*PSTR;
            const __nv_bfloat16* lBrow = Hlo + (m0+g+8)*PSTR;
            #pragma unroll
            for(int ks = 0; ks < 4; ks++){
                int kc = ks*16 + 2*t;
                uint32_t ah0 = *(const uint32_t*)(hArow + kc);
                uint32_t ah1 = *(const uint32_t*)(hBrow + kc);
                uint32_t ah2 = *(const uint32_t*)(hArow + kc + 8);
                uint32_t ah3 = *(const uint32_t*)(hBrow + kc + 8);
                uint32_t al0 = *(const uint32_t*)(lArow + kc);
                uint32_t al1 = *(const uint32_t*)(lBrow + kc);
                uint32_t al2 = *(const uint32_t*)(lArow + kc + 8);
                uint32_t al3 = *(const uint32_t*)(lBrow + kc + 8);
                #pragma unroll
                for(int nt = 0; nt < 8; nt++){
                    uint4 wf = Wfs[(cb + nt*8 + g)*20 + ks*4 + t];
                    mma_bf16(accr[jj][nt][0], accr[jj][nt][1], accr[jj][nt][2], accr[jj][nt][3],
                             ah0, ah1, ah2, ah3, wf.x, wf.y);
                    mma_bf16(accr[jj][nt][0], accr[jj][nt][1], accr[jj][nt][2], accr[jj][nt][3],
                             al0, al1, al2, al3, wf.x, wf.y);
                    mma_bf16(accr[jj][nt][0], accr[jj][nt][1], accr[jj][nt][2], accr[jj][nt][3],
                             ah0, ah1, ah2, ah3, wf.z, wf.w);
                }
            }
        }
    }
    // need perm in registers before oS overlay clobbers... perm region is OUTSIDE overlay (84480 >= 65536) - safe.
    __syncthreads();               // Wf + H dead from here

    // phase 5: zero oS, scatter, store
    {
        float4 z4 = make_float4(0.f,0.f,0.f,0.f);
        for(int i = tid; i < 4096; i += 256) ((float4*)oS)[i] = z4;
    }
    __syncthreads();

    #pragma unroll
    for(int jj = 0; jj < 2; jj++){
        int j = w + jj*8;
        if(j < njobs){
            int chunk = j >> 1, cb = (j & 1)*64;
            int slotA = chunk*16 + g;
            int slotB = slotA + 8;
            int vA = (slotA < M) ? permS[slotA] : -1;
            int vB = (slotB < M) ? permS[slotB] : -1;
            #pragma unroll
            for(int nt = 0; nt < 8; nt++){
                int ch = cb + nt*8 + 2*t;
                int sw = (ch >> 3) & 15;
                float b0 = c2S[ch], b1 = c2S[ch+1];
                if(vA >= 0){
                    int idx = (((vA >> 2) ^ sw) << 2) + (vA & 3);
                    oS[ch*128 + idx]     = fmaxf(accr[jj][nt][0] + b0, 0.f);
                    oS[(ch+1)*128 + idx] = fmaxf(accr[jj][nt][1] + b1, 0.f);
                }
                if(vB >= 0){
                    int idx = (((vB >> 2) ^ sw) << 2) + (vB & 3);
                    oS[ch*128 + idx]     = fmaxf(accr[jj][nt][2] + b0, 0.f);
                    oS[(ch+1)*128 + idx] = fmaxf(accr[jj][nt][3] + b1, 0.f);
                }
            }
        }
    }
    __syncthreads();

    for(int i = tid; i < 4096; i += 256){
        int c = i >> 5, vq = i & 31;
        int s = (c >> 3) & 15;
        float4 v = *(const float4*)(oS + c*128 + ((vq ^ s) << 2));
        __stcs((float4*)(ob + (size_t)c*G3) + vq, v);
    }
}

// ---------------- launch ----------------
extern "C" void kernel_launch(void* const* d_in, const int* in_sizes, int n_in,
                              void* d_out, int out_size){
    const float* pc  = (const float*)d_in[0];
    const float* W1  = (const float*)d_in[1];
    const float* b1  = (const float*)d_in[2];
    const float* g1  = (const float*)d_in[3];
    const float* be1 = (const float*)d_in[4];
    const float* rm1 = (const float*)d_in[5];
    const float* rv1 = (const float*)d_in[6];
    const float* W2  = (const float*)d_in[7];
    const float* b2  = (const float*)d_in[8];
    const float* g2  = (const float*)d_in[9];
    const float* be2 = (const float*)d_in[10];
    const float* rm2 = (const float*)d_in[11];
    const float* rv2 = (const float*)d_in[12];

    cudaFuncSetAttribute(k_tile, cudaFuncAttributeMaxDynamicSharedMemorySize, SB_BYTES);

    k_prep<<<8448, 256>>>(W1,b1,g1,be1,rm1,rv1,W2,b2,g2,be2,rm2,rv2, pc);
    k_voxel<<<dim3(782,4), 256>>>(pc);
    k_tile<<<NTILES, 256, SB_BYTES>>>((float*)d_out);
}

// round 15
// speedup vs baseline: 1.2550x; 1.0127x over previous
#include <cuda_runtime.h>
#include <cuda_bf16.h>
#include <cstdint>
#include <cstddef>

typedef unsigned long long ull;

#define GDIM 64
#define G3 (GDIM*GDIM*GDIM)
#define BATCH 4
#define NPTS 200000
#define MAXPV 35.0f
#define NTILES 8192
#define PSTR 72

// ---------------- scratch ----------------
__device__ __align__(16) float g_accum[BATCH*G3*8];
__device__ float g_mm2[BATCH*64*6];
__device__ float g_A1t[7*64];
__device__ float g_c1[64];
__device__ float g_c2[128];
__device__ __align__(16) uint4 g_Wf[128*20];   // fragment-packed hi/lo weights, stride 20 uint4/channel

// ---------------- helpers ----------------
__device__ __forceinline__ void red4(float* addr, float x, float y, float z, float w){
    asm volatile("red.global.add.v4.f32 [%0], {%1,%2,%3,%4};"
                 :: "l"(addr), "f"(x), "f"(y), "f"(z), "f"(w) : "memory");
}
__device__ __forceinline__ void mma_bf16(float& c0, float& c1, float& c2, float& c3,
                                         uint32_t a0, uint32_t a1, uint32_t a2, uint32_t a3,
                                         uint32_t b0, uint32_t b1){
    asm volatile("mma.sync.aligned.m16n8k16.row.col.f32.bf16.bf16.f32 "
                 "{%0,%1,%2,%3}, {%4,%5,%6,%7}, {%8,%9}, {%0,%1,%2,%3};"
                 : "+f"(c0), "+f"(c1), "+f"(c2), "+f"(c3)
                 : "r"(a0), "r"(a1), "r"(a2), "r"(a3), "r"(b0), "r"(b1));
}

// ---------------- kernel 1: prep (coarsened zero + weights + minmax partials) ----------------
__global__ void k_prep(const float* __restrict__ W1, const float* __restrict__ b1,
                       const float* __restrict__ g1, const float* __restrict__ be1,
                       const float* __restrict__ rm1, const float* __restrict__ rv1,
                       const float* __restrict__ W2, const float* __restrict__ b2,
                       const float* __restrict__ g2, const float* __restrict__ be2,
                       const float* __restrict__ rm2, const float* __restrict__ rv2,
                       const float* __restrict__ pc){
    if(blockIdx.x < 2048){
        int i = blockIdx.x*256 + threadIdx.x;
        float4 z = make_float4(0.f,0.f,0.f,0.f);
        #pragma unroll
        for(int r = 0; r < 4; r++)
            ((float4*)g_accum)[i + r*524288] = z;
        if(blockIdx.x == 0){
            int t = threadIdx.x;
            if(t < 64){
                float s = g1[t] / sqrtf(rv1[t] + 1e-5f);
                g_c1[t] = (b1[t] - rm1[t]) * s + be1[t];
                #pragma unroll
                for(int k = 0; k < 7; k++) g_A1t[k*64 + t] = W1[t*7 + k] * s;
            }
            if(t < 128){
                float s = g2[t] / sqrtf(rv2[t] + 1e-5f);
                g_c2[t] = (b2[t] - rm2[t]) * s + be2[t];
                uint32_t whi[32], wlo[32];
                for(int kw = 0; kw < 32; kw++){
                    float wa = W2[t*64 + 2*kw    ] * s;
                    float wb = W2[t*64 + 2*kw + 1] * s;
                    __nv_bfloat16 ha = __float2bfloat16(wa);
                    __nv_bfloat16 hb = __float2bfloat16(wb);
                    __nv_bfloat16 la = __float2bfloat16(wa - __bfloat162float(ha));
                    __nv_bfloat16 lb = __float2bfloat16(wb - __bfloat162float(hb));
                    whi[kw] = (uint32_t)*(uint16_t*)&ha | ((uint32_t)*(uint16_t*)&hb << 16);
                    wlo[kw] = (uint32_t)*(uint16_t*)&la | ((uint32_t)*(uint16_t*)&lb << 16);
                }
                for(int ks = 0; ks < 4; ks++)
                    for(int tt = 0; tt < 4; tt++){
                        int ws = ks*8 + tt;
                        uint4 f;
                        f.x = whi[ws]; f.y = whi[ws+4];
                        f.z = wlo[ws]; f.w = wlo[ws+4];
                        g_Wf[t*20 + ks*4 + tt] = f;
                    }
            }
        }
        return;
    }
    int m = blockIdx.x - 2048;          // 0..255
    int b = m >> 6, mloc = m & 63;
    const float* px = pc + b*6*NPTS;
    float mn0= 3.4e38f, mn1= 3.4e38f, mn2= 3.4e38f;
    float mx0=-3.4e38f, mx1=-3.4e38f, mx2=-3.4e38f;
    for(int n = mloc*256 + threadIdx.x; n < NPTS; n += 64*256){
        float x = px[n], y = px[NPTS+n], z = px[2*NPTS+n];
        mn0 = fminf(mn0,x); mx0 = fmaxf(mx0,x);
        mn1 = fminf(mn1,y); mx1 = fmaxf(mx1,y);
        mn2 = fminf(mn2,z); mx2 = fmaxf(mx2,z);
    }
    #pragma unroll
    for(int s = 16; s; s >>= 1){
        mn0 = fminf(mn0, __shfl_xor_sync(~0u, mn0, s));
        mn1 = fminf(mn1, __shfl_xor_sync(~0u, mn1, s));
        mn2 = fminf(mn2, __shfl_xor_sync(~0u, mn2, s));
        mx0 = fmaxf(mx0, __shfl_xor_sync(~0u, mx0, s));
        mx1 = fmaxf(mx1, __shfl_xor_sync(~0u, mx1, s));
        mx2 = fmaxf(mx2, __shfl_xor_sync(~0u, mx2, s));
    }
    __shared__ float wred[8][6];
    int wid = threadIdx.x >> 5;
    if((threadIdx.x & 31) == 0){
        wred[wid][0]=mn0; wred[wid][1]=mn1; wred[wid][2]=mn2;
        wred[wid][3]=mx0; wred[wid][4]=mx1; wred[wid][5]=mx2;
    }
    __syncthreads();
    if(threadIdx.x < 6){
        int c = threadIdx.x;
        bool isMin = c < 3;
        float acc = wred[0][c];
        #pragma unroll
        for(int w = 1; w < 8; w++) acc = isMin ? fminf(acc, wred[w][c]) : fmaxf(acc, wred[w][c]);
        g_mm2[m*6 + c] = acc;
    }
}

// ---------------- kernel 2: voxel scatter ----------------
__global__ void k_voxel(const float* __restrict__ pc){
    int b = blockIdx.y;
    __shared__ float red[6];
    {
        int wid = threadIdx.x >> 5, lid = threadIdx.x & 31;
        if(wid < 6){
            bool isMin = wid < 3;
            float acc = isMin ? 3.4e38f : -3.4e38f;
            for(int m = lid; m < 64; m += 32){
                float v = g_mm2[(b*64 + m)*6 + wid];
                acc = isMin ? fminf(acc, v) : fmaxf(acc, v);
            }
            #pragma unroll
            for(int s = 16; s; s >>= 1){
                float o = __shfl_xor_sync(~0u, acc, s);
                acc = isMin ? fminf(acc, o) : fmaxf(acc, o);
            }
            if(lid == 0) red[wid] = acc;
        }
        __syncthreads();
    }
    float mn0 = red[0], mn1 = red[1], mn2 = red[2];
    float d0 = red[3] - mn0 + 1e-7f;
    float d1 = red[4] - mn1 + 1e-7f;
    float d2 = red[5] - mn2 + 1e-7f;

    const float* p = pc + b*6*NPTS;
    float* acc = g_accum + (size_t)b*G3*8;
    for(int n = blockIdx.x*blockDim.x + threadIdx.x; n < NPTS; n += gridDim.x*blockDim.x){
        float x = p[n], y = p[NPTS+n], z = p[2*NPTS+n];
        float r = p[3*NPTS+n], g = p[4*NPTS+n], bl = p[5*NPTS+n];
        float tx = __fmul_rn(__fdiv_rn(x - mn0, d0), 63.0f);
        float ty = __fmul_rn(__fdiv_rn(y - mn1, d1), 63.0f);
        float tz = __fmul_rn(__fdiv_rn(z - mn2, d2), 63.0f);
        tx = fminf(fmaxf(tx, 0.0f), 62.9999f);
        ty = fminf(fmaxf(ty, 0.0f), 62.9999f);
        tz = fminf(fmaxf(tz, 0.0f), 62.9999f);
        int flat = (((int)tx)*GDIM + (int)ty)*GDIM + (int)tz;
        float* v = acc + (size_t)flat*8;
        red4(v,     x, y, z, 1.0f);
        red4(v + 4, r, g, bl, 0.0f);
    }
}

// ---------------- kernel 3: fused per-tile MLP + masked output store ----------------
#define SB_WF    0                       // 40960
#define SB_HHI   40960                   // 18432
#define SB_HLO   59392                   // 18432 -> 77824
#define SB_FEAT  77824                   // -> 81920
#define SB_A1T   81920                   // -> 83712
#define SB_C1    83712                   // -> 83968
#define SB_C2    83968                   // -> 84480
#define SB_PERM  84480                   // -> 84992
#define SB_AUX   84992                   // 16 ints -> 85056
#define SB_BYTES 85056

__global__ void __launch_bounds__(256, 2) k_tile(float* __restrict__ out){
    extern __shared__ char smc[];
    uint4* Wfs = (uint4*)(smc + SB_WF);
    __nv_bfloat16* Hhi = (__nv_bfloat16*)(smc + SB_HHI);
    __nv_bfloat16* Hlo = (__nv_bfloat16*)(smc + SB_HLO);
    float* featS = (float*)(smc + SB_FEAT);
    float* A1tS  = (float*)(smc + SB_A1T);
    float* c1S   = (float*)(smc + SB_C1);
    float* c2S   = (float*)(smc + SB_C2);
    int*   permS = (int*)(smc + SB_PERM);
    int*   auxS  = (int*)(smc + SB_AUX);
    float* oS    = (float*)smc;          // overlay (first 64KB)

    int tid = threadIdx.x;
    int tile = blockIdx.x;
    int b = tile >> 11;
    int vbase = (tile & 2047) << 7;
    const float* acc = g_accum + ((size_t)b*G3 + vbase)*8;
    float* ob = out + (size_t)b*128*G3 + vbase;
    float4 z4 = make_float4(0.f,0.f,0.f,0.f);

    // phase 1: load accumulators, ballot occupancy
    float4 p0 = make_float4(0,0,0,0), p1 = make_float4(0,0,0,0);
    int occ = 0;
    if(tid < 128){
        p0 = *(const float4*)(acc + tid*8);
        p1 = *(const float4*)(acc + tid*8 + 4);
        occ = p0.w > 0.f;
    }
    unsigned bal = __ballot_sync(0xFFFFFFFFu, occ);
    if(tid < 128 && (tid & 31) == 0){
        auxS[tid >> 5] = __popc(bal);
        auxS[8 + (tid >> 5)] = (int)bal;
    }
    __syncthreads();
    int n0 = auxS[0], n1 = auxS[1], n2 = auxS[2], n3 = auxS[3];
    int M = n0 + n1 + n2 + n3;

    if(M == 0){
        for(int i = tid; i < 4096; i += 256){
            int c = i >> 5, q = i & 31;
            __stcs((float4*)(ob + (size_t)c*G3) + q, z4);
        }
        return;
    }

    // quad occupancy mask (warp 0): quad q covers voxels 4q..4q+3
    if(tid < 32){
        unsigned wball = (unsigned)auxS[8 + (tid >> 3)];
        unsigned nib = (wball >> ((tid & 7)*4)) & 0xFu;
        unsigned qb = __ballot_sync(0xFFFFFFFFu, nib != 0u);
        if(tid == 0) auxS[12] = (int)qb;
    }

    // phase 2: features + perm + weight staging
    if(occ){
        float dn = fmaxf(p0.w, 1.0f);
        float* f = featS + tid*8;
        f[0] = __fdiv_rn(p0.x, dn);
        f[1] = __fdiv_rn(p0.y, dn);
        f[2] = __fdiv_rn(p0.z, dn);
        f[3] = __fdiv_rn(fminf(p0.w, MAXPV), MAXPV);
        f[4] = __fdiv_rn(p1.x, dn);
        f[5] = __fdiv_rn(p1.y, dn);
        f[6] = __fdiv_rn(p1.z, dn);
        f[7] = 0.f;
        int w = tid >> 5;
        int off = (w > 0 ? n0 : 0) + (w > 1 ? n1 : 0) + (w > 2 ? n2 : 0);
        permS[off + __popc(bal & ((1u << (tid & 31)) - 1u))] = tid;
    }
    for(int i = tid; i < 2048; i += 256){
        int c = i >> 4, r = i & 15;
        Wfs[c*20 + r] = g_Wf[c*20 + r];
    }
    for(int i = tid; i < 448; i += 256) A1tS[i] = g_A1t[i];
    if(tid < 64)  c1S[tid] = g_c1[tid];
    if(tid < 128) c2S[tid] = g_c2[tid];
    __syncthreads();

    // phase 3: layer 1 for occupied slots -> bf16 hi/lo planes
    for(int i = tid; i < M*32; i += 256){
        int slot = i >> 5, jp = (i & 31)*2;
        int v = permS[slot];
        float s0 = c1S[jp], s1 = c1S[jp+1];
        const float* f = featS + v*8;
        #pragma unroll
        for(int k = 0; k < 7; k++){
            float fv = f[k];
            s0 = fmaf(fv, A1tS[k*64 + jp],   s0);
            s1 = fmaf(fv, A1tS[k*64 + jp+1], s1);
        }
        float h0 = fmaxf(s0, 0.f), h1 = fmaxf(s1, 0.f);
        __nv_bfloat16 h0h = __float2bfloat16(h0);
        __nv_bfloat16 h1h = __float2bfloat16(h1);
        __nv_bfloat16 h0l = __float2bfloat16(h0 - __bfloat162float(h0h));
        __nv_bfloat16 h1l = __float2bfloat16(h1 - __bfloat162float(h1h));
        uint32_t hiw = (uint32_t)*(uint16_t*)&h0h | ((uint32_t)*(uint16_t*)&h1h << 16);
        uint32_t low = (uint32_t)*(uint16_t*)&h0l | ((uint32_t)*(uint16_t*)&h1l << 16);
        *(uint32_t*)(Hhi + slot*PSTR + jp) = hiw;
        *(uint32_t*)(Hlo + slot*PSTR + jp) = low;
    }
    __syncthreads();

    // phase 4: HMMA jobs. job j: chunk=j>>1 (16 slots), channel half=(j&1)*64.
    int nchunk = (M + 15) >> 4;
    int njobs = nchunk*2;
    int w = tid >> 5, lane = tid & 31;
    int g = lane >> 2, t = lane & 3;

    float accr[2][8][4];
    #pragma unroll
    for(int jj = 0; jj < 2; jj++)
        #pragma unroll
        for(int nt = 0; nt < 8; nt++)
            #pragma unroll
            for(int r = 0; r < 4; r++) accr[jj][nt][r] = 0.f;

    #pragma unroll
    for(int jj = 0; jj < 2; jj++){
        int j = w + jj*8;
        if(j < njobs){
            int chunk = j >> 1, cb = (j & 1)*64;
            int m0 = chunk*16;
            const __nv_bfloat16* hArow = Hhi + (m0+g)*PSTR;
            const __nv_bfloat16* hBrow = Hhi + (m0+g+8)*PSTR;
            const __nv_bfloat16* lArow = Hlo + (m0+g)*PSTR;
            const __nv_bfloat16* lBrow = Hlo + (m0+g+8)*PSTR;
            #pragma unroll
            for(int ks = 0; ks < 4; ks++){
                int kc = ks*16 + 2*t;
                uint32_t ah0 = *(const uint32_t*)(hArow + kc);
                uint32_t ah1 = *(const uint32_t*)(hBrow + kc);
                uint32_t ah2 = *(const uint32_t*)(hArow + kc + 8);
                uint32_t ah3 = *(const uint32_t*)(hBrow + kc + 8);
                uint32_t al0 = *(const uint32_t*)(lArow + kc);
                uint32_t al1 = *(const uint32_t*)(lBrow + kc);
                uint32_t al2 = *(const uint32_t*)(lArow + kc + 8);
                uint32_t al3 = *(const uint32_t*)(lBrow + kc + 8);
                #pragma unroll
                for(int nt = 0; nt < 8; nt++){
                    uint4 wf = Wfs[(cb + nt*8 + g)*20 + ks*4 + t];
                    mma_bf16(accr[jj][nt][0], accr[jj][nt][1], accr[jj][nt][2], accr[jj][nt][3],
                             ah0, ah1, ah2, ah3, wf.x, wf.y);
                    mma_bf16(accr[jj][nt][0], accr[jj][nt][1], accr[jj][nt][2], accr[jj][nt][3],
                             al0, al1, al2, al3, wf.x, wf.y);
                    mma_bf16(accr[jj][nt][0], accr[jj][nt][1], accr[jj][nt][2], accr[jj][nt][3],
                             ah0, ah1, ah2, ah3, wf.z, wf.w);
                }
            }
        }
    }
    unsigned qmask = (unsigned)auxS[12];
    __syncthreads();               // Wf + H dead from here (perm/aux outside 64KB overlay)

    // phase 5: masked zero, scatter, masked store
    for(int i = tid; i < 4096; i += 256){
        int c = i >> 5, vq = i & 31;
        if((qmask >> vq) & 1u)
            *(float4*)(oS + c*128 + ((vq ^ ((c >> 3) & 15)) << 2)) = z4;
    }
    __syncthreads();

    #pragma unroll
    for(int jj = 0; jj < 2; jj++){
        int j = w + jj*8;
        if(j < njobs){
            int chunk = j >> 1, cb = (j & 1)*64;
            int slotA = chunk*16 + g;
            int slotB = slotA + 8;
            int vA = (slotA < M) ? permS[slotA] : -1;
            int vB = (slotB < M) ? permS[slotB] : -1;
            #pragma unroll
            for(int nt = 0; nt < 8; nt++){
                int ch = cb + nt*8 + 2*t;
                int sw = (ch >> 3) & 15;
                float b0 = c2S[ch], b1 = c2S[ch+1];
                if(vA >= 0){
                    int idx = (((vA >> 2) ^ sw) << 2) + (vA & 3);
                    oS[ch*128 + idx]     = fmaxf(accr[jj][nt][0] + b0, 0.f);
                    oS[(ch+1)*128 + idx] = fmaxf(accr[jj][nt][1] + b1, 0.f);
                }
                if(vB >= 0){
                    int idx = (((vB >> 2) ^ sw) << 2) + (vB & 3);
                    oS[ch*128 + idx]     = fmaxf(accr[jj][nt][2] + b0, 0.f);
                    oS[(ch+1)*128 + idx] = fmaxf(accr[jj][nt][3] + b1, 0.f);
                }
            }
        }
    }
    __syncthreads();

    for(int i = tid; i < 4096; i += 256){
        int c = i >> 5, vq = i & 31;
        float4 v = ((qmask >> vq) & 1u)
            ? *(const float4*)(oS + c*128 + ((vq ^ ((c >> 3) & 15)) << 2)) : z4;
        __stcs((float4*)(ob + (size_t)c*G3) + vq, v);
    }
}

// ---------------- launch ----------------
extern "C" void kernel_launch(void* const* d_in, const int* in_sizes, int n_in,
                              void* d_out, int out_size){
    const float* pc  = (const float*)d_in[0];
    const float* W1  = (const float*)d_in[1];
    const float* b1  = (const float*)d_in[2];
    const float* g1  = (const float*)d_in[3];
    const float* be1 = (const float*)d_in[4];
    const float* rm1 = (const float*)d_in[5];
    const float* rv1 = (const float*)d_in[6];
    const float* W2  = (const float*)d_in[7];
    const float* b2  = (const float*)d_in[8];
    const float* g2  = (const float*)d_in[9];
    const float* be2 = (const float*)d_in[10];
    const float* rm2 = (const float*)d_in[11];
    const float* rv2 = (const float*)d_in[12];

    cudaFuncSetAttribute(k_tile, cudaFuncAttributeMaxDynamicSharedMemorySize, SB_BYTES);

    k_prep<<<2304, 256>>>(W1,b1,g1,be1,rm1,rv1,W2,b2,g2,be2,rm2,rv2, pc);
    k_voxel<<<dim3(782,4), 256>>>(pc);
    k_tile<<<NTILES, 256, SB_BYTES>>>((float*)d_out);
}

// round 16
// speedup vs baseline: 1.3880x; 1.1059x over previous
#include <cuda_runtime.h>
#include <cuda_bf16.h>
#include <cstdint>
#include <cstddef>

typedef unsigned long long ull;

#define GDIM 64
#define G3 (GDIM*GDIM*GDIM)
#define BATCH 4
#define NPTS 200000
#define MAXPV 35.0f
#define NTILES 8192
#define PSTR 72

// ---------------- scratch ----------------
__device__ __align__(16) float g_accum[BATCH*G3*8];
__device__ float g_mm2[BATCH*64*6];
__device__ float g_A1t[7*64];
__device__ float g_c1[64];
__device__ float g_c2[128];
__device__ __align__(16) uint4 g_Wf[128*20];   // fragment-packed hi/lo weights, stride 20 uint4/channel

// ---------------- helpers ----------------
__device__ __forceinline__ void red4(float* addr, float x, float y, float z, float w){
    asm volatile("red.global.add.v4.f32 [%0], {%1,%2,%3,%4};"
                 :: "l"(addr), "f"(x), "f"(y), "f"(z), "f"(w) : "memory");
}
__device__ __forceinline__ void mma_bf16(float& c0, float& c1, float& c2, float& c3,
                                         uint32_t a0, uint32_t a1, uint32_t a2, uint32_t a3,
                                         uint32_t b0, uint32_t b1){
    asm volatile("mma.sync.aligned.m16n8k16.row.col.f32.bf16.bf16.f32 "
                 "{%0,%1,%2,%3}, {%4,%5,%6,%7}, {%8,%9}, {%0,%1,%2,%3};"
                 : "+f"(c0), "+f"(c1), "+f"(c2), "+f"(c3)
                 : "r"(a0), "r"(a1), "r"(a2), "r"(a3), "r"(b0), "r"(b1));
}
__device__ __forceinline__ void cpasync16(unsigned saddr, const void* gaddr){
    asm volatile("cp.async.cg.shared.global [%0], [%1], 16;" :: "r"(saddr), "l"(gaddr));
}
__device__ __forceinline__ void cpasync_commit(){ asm volatile("cp.async.commit_group;"); }
__device__ __forceinline__ void cpasync_wait0(){ asm volatile("cp.async.wait_group 0;"); }
__device__ __forceinline__ uint32_t pack_bf16x2(float a, float b){
    __nv_bfloat16 ba = __float2bfloat16(a);
    __nv_bfloat16 bb = __float2bfloat16(b);
    return (uint32_t)*(uint16_t*)&ba | ((uint32_t)*(uint16_t*)&bb << 16);
}

// ---------------- kernel 1: prep ----------------
// blocks [0,2048): zero accum (4 float4/thread)
// block 2048: parallel weight fuse (2048 fragments over 256 threads) + biases + A1t
// blocks [2049,2305): minmax partials
__global__ void k_prep(const float* __restrict__ W1, const float* __restrict__ b1,
                       const float* __restrict__ g1, const float* __restrict__ be1,
                       const float* __restrict__ rm1, const float* __restrict__ rv1,
                       const float* __restrict__ W2, const float* __restrict__ b2,
                       const float* __restrict__ g2, const float* __restrict__ be2,
                       const float* __restrict__ rm2, const float* __restrict__ rv2,
                       const float* __restrict__ pc){
    if(blockIdx.x < 2048){
        int i = blockIdx.x*256 + threadIdx.x;
        float4 z = make_float4(0.f,0.f,0.f,0.f);
        #pragma unroll
        for(int r = 0; r < 4; r++)
            ((float4*)g_accum)[i + r*524288] = z;
        return;
    }
    if(blockIdx.x == 2048){
        int t = threadIdx.x;
        // layer-1 fuse (64 channels; short loops, parallel across threads)
        if(t < 64){
            float s = g1[t] / sqrtf(rv1[t] + 1e-5f);
            g_c1[t] = (b1[t] - rm1[t]) * s + be1[t];
            #pragma unroll
            for(int k = 0; k < 7; k++) g_A1t[k*64 + t] = W1[t*7 + k] * s;
        }
        if(t < 128){
            float s = g2[t] / sqrtf(rv2[t] + 1e-5f);
            g_c2[t] = (b2[t] - rm2[t]) * s + be2[t];
        }
        // layer-2 fragment packing: 2048 fragments, 8 per thread, independent
        #pragma unroll
        for(int r = 0; r < 8; r++){
            int fid = t + r*256;
            int c = fid >> 4, rem = fid & 15;
            int ks = rem >> 2, tt = rem & 3;
            float s = g2[c] / sqrtf(rv2[c] + 1e-5f);
            int kwA = ks*8 + tt, kwB = kwA + 4;
            float wa0 = W2[c*64 + 2*kwA    ] * s;
            float wa1 = W2[c*64 + 2*kwA + 1] * s;
            float wb0 = W2[c*64 + 2*kwB    ] * s;
            float wb1 = W2[c*64 + 2*kwB + 1] * s;
            __nv_bfloat16 ha0 = __float2bfloat16(wa0);
            __nv_bfloat16 ha1 = __float2bfloat16(wa1);
            __nv_bfloat16 hb0 = __float2bfloat16(wb0);
            __nv_bfloat16 hb1 = __float2bfloat16(wb1);
            uint4 f;
            f.x = (uint32_t)*(uint16_t*)&ha0 | ((uint32_t)*(uint16_t*)&ha1 << 16);
            f.y = (uint32_t)*(uint16_t*)&hb0 | ((uint32_t)*(uint16_t*)&hb1 << 16);
            f.z = pack_bf16x2(wa0 - __bfloat162float(ha0), wa1 - __bfloat162float(ha1));
            f.w = pack_bf16x2(wb0 - __bfloat162float(hb0), wb1 - __bfloat162float(hb1));
            g_Wf[c*20 + ks*4 + tt] = f;
        }
        return;
    }
    int m = blockIdx.x - 2049;          // 0..255
    int b = m >> 6, mloc = m & 63;
    const float* px = pc + b*6*NPTS;
    float mn0= 3.4e38f, mn1= 3.4e38f, mn2= 3.4e38f;
    float mx0=-3.4e38f, mx1=-3.4e38f, mx2=-3.4e38f;
    for(int n = mloc*256 + threadIdx.x; n < NPTS; n += 64*256){
        float x = px[n], y = px[NPTS+n], z = px[2*NPTS+n];
        mn0 = fminf(mn0,x); mx0 = fmaxf(mx0,x);
        mn1 = fminf(mn1,y); mx1 = fmaxf(mx1,y);
        mn2 = fminf(mn2,z); mx2 = fmaxf(mx2,z);
    }
    #pragma unroll
    for(int s = 16; s; s >>= 1){
        mn0 = fminf(mn0, __shfl_xor_sync(~0u, mn0, s));
        mn1 = fminf(mn1, __shfl_xor_sync(~0u, mn1, s));
        mn2 = fminf(mn2, __shfl_xor_sync(~0u, mn2, s));
        mx0 = fmaxf(mx0, __shfl_xor_sync(~0u, mx0, s));
        mx1 = fmaxf(mx1, __shfl_xor_sync(~0u, mx1, s));
        mx2 = fmaxf(mx2, __shfl_xor_sync(~0u, mx2, s));
    }
    __shared__ float wred[8][6];
    int wid = threadIdx.x >> 5;
    if((threadIdx.x & 31) == 0){
        wred[wid][0]=mn0; wred[wid][1]=mn1; wred[wid][2]=mn2;
        wred[wid][3]=mx0; wred[wid][4]=mx1; wred[wid][5]=mx2;
    }
    __syncthreads();
    if(threadIdx.x < 6){
        int c = threadIdx.x;
        bool isMin = c < 3;
        float acc = wred[0][c];
        #pragma unroll
        for(int w = 1; w < 8; w++) acc = isMin ? fminf(acc, wred[w][c]) : fmaxf(acc, wred[w][c]);
        g_mm2[m*6 + c] = acc;
    }
}

// ---------------- kernel 2: voxel scatter (unchanged iteration pattern) ----------------
__global__ void k_voxel(const float* __restrict__ pc){
    int b = blockIdx.y;
    __shared__ float red[6];
    {
        int wid = threadIdx.x >> 5, lid = threadIdx.x & 31;
        if(wid < 6){
            bool isMin = wid < 3;
            float acc = isMin ? 3.4e38f : -3.4e38f;
            for(int m = lid; m < 64; m += 32){
                float v = g_mm2[(b*64 + m)*6 + wid];
                acc = isMin ? fminf(acc, v) : fmaxf(acc, v);
            }
            #pragma unroll
            for(int s = 16; s; s >>= 1){
                float o = __shfl_xor_sync(~0u, acc, s);
                acc = isMin ? fminf(acc, o) : fmaxf(acc, o);
            }
            if(lid == 0) red[wid] = acc;
        }
        __syncthreads();
    }
    float mn0 = red[0], mn1 = red[1], mn2 = red[2];
    float d0 = red[3] - mn0 + 1e-7f;
    float d1 = red[4] - mn1 + 1e-7f;
    float d2 = red[5] - mn2 + 1e-7f;

    const float* p = pc + b*6*NPTS;
    float* acc = g_accum + (size_t)b*G3*8;
    for(int n = blockIdx.x*blockDim.x + threadIdx.x; n < NPTS; n += gridDim.x*blockDim.x){
        float x = p[n], y = p[NPTS+n], z = p[2*NPTS+n];
        float r = p[3*NPTS+n], g = p[4*NPTS+n], bl = p[5*NPTS+n];
        float tx = __fmul_rn(__fdiv_rn(x - mn0, d0), 63.0f);
        float ty = __fmul_rn(__fdiv_rn(y - mn1, d1), 63.0f);
        float tz = __fmul_rn(__fdiv_rn(z - mn2, d2), 63.0f);
        tx = fminf(fmaxf(tx, 0.0f), 62.9999f);
        ty = fminf(fmaxf(ty, 0.0f), 62.9999f);
        tz = fminf(fmaxf(tz, 0.0f), 62.9999f);
        int flat = (((int)tx)*GDIM + (int)ty)*GDIM + (int)tz;
        float* v = acc + (size_t)flat*8;
        red4(v,     x, y, z, 1.0f);
        red4(v + 4, r, g, bl, 0.0f);
    }
}

// ---------------- kernel 3: fused per-tile MLP + masked output store ----------------
#define SB_WF    0                       // 40960
#define SB_HHI   40960                   // 18432
#define SB_HLO   59392                   // 18432 -> 77824
#define SB_FEAT  77824                   // -> 81920
#define SB_A1T   81920                   // -> 83712
#define SB_C1    83712                   // -> 83968
#define SB_C2    83968                   // -> 84480
#define SB_PERM  84480                   // -> 84992
#define SB_AUX   84992                   // 16 ints -> 85056
#define SB_BYTES 85056

__global__ void __launch_bounds__(256, 2) k_tile(float* __restrict__ out){
    extern __shared__ char smc[];
    uint4* Wfs = (uint4*)(smc + SB_WF);
    __nv_bfloat16* Hhi = (__nv_bfloat16*)(smc + SB_HHI);
    __nv_bfloat16* Hlo = (__nv_bfloat16*)(smc + SB_HLO);
    float* featS = (float*)(smc + SB_FEAT);
    float* A1tS  = (float*)(smc + SB_A1T);
    float* c1S   = (float*)(smc + SB_C1);
    float* c2S   = (float*)(smc + SB_C2);
    int*   permS = (int*)(smc + SB_PERM);
    int*   auxS  = (int*)(smc + SB_AUX);
    float* oS    = (float*)smc;          // overlay (first 64KB)

    int tid = threadIdx.x;
    int tile = blockIdx.x;
    int b = tile >> 11;
    int vbase = (tile & 2047) << 7;
    const float* acc = g_accum + ((size_t)b*G3 + vbase)*8;
    float* ob = out + (size_t)b*128*G3 + vbase;
    float4 z4 = make_float4(0.f,0.f,0.f,0.f);

    // weight prefetch via cp.async, overlapped with phases 1-3
    {
        unsigned sb = (unsigned)__cvta_generic_to_shared(smc);
        #pragma unroll
        for(int r = 0; r < 8; r++){
            int i = tid + r*256;
            int c = i >> 4, q = i & 15;
            cpasync16(sb + SB_WF + (unsigned)(c*20 + q)*16, &g_Wf[c*20 + q]);
        }
        cpasync_commit();
    }

    // phase 1: load accumulators, ballot occupancy
    float4 p0 = make_float4(0,0,0,0), p1 = make_float4(0,0,0,0);
    int occ = 0;
    if(tid < 128){
        p0 = *(const float4*)(acc + tid*8);
        p1 = *(const float4*)(acc + tid*8 + 4);
        occ = p0.w > 0.f;
    }
    unsigned bal = __ballot_sync(0xFFFFFFFFu, occ);
    if(tid < 128 && (tid & 31) == 0){
        auxS[tid >> 5] = __popc(bal);
        auxS[8 + (tid >> 5)] = (int)bal;
    }
    __syncthreads();
    int n0 = auxS[0], n1 = auxS[1], n2 = auxS[2], n3 = auxS[3];
    int M = n0 + n1 + n2 + n3;

    if(M == 0){
        for(int i = tid; i < 4096; i += 256){
            int c = i >> 5, q = i & 31;
            __stcs((float4*)(ob + (size_t)c*G3) + q, z4);
        }
        return;
    }

    // quad occupancy mask (warp 0): quad q covers voxels 4q..4q+3
    if(tid < 32){
        unsigned wball = (unsigned)auxS[8 + (tid >> 3)];
        unsigned nib = (wball >> ((tid & 7)*4)) & 0xFu;
        unsigned qb = __ballot_sync(0xFFFFFFFFu, nib != 0u);
        if(tid == 0) auxS[12] = (int)qb;
    }

    // phase 2: features + perm + small consts
    if(occ){
        float dn = fmaxf(p0.w, 1.0f);
        float* f = featS + tid*8;
        f[0] = __fdiv_rn(p0.x, dn);
        f[1] = __fdiv_rn(p0.y, dn);
        f[2] = __fdiv_rn(p0.z, dn);
        f[3] = __fdiv_rn(fminf(p0.w, MAXPV), MAXPV);
        f[4] = __fdiv_rn(p1.x, dn);
        f[5] = __fdiv_rn(p1.y, dn);
        f[6] = __fdiv_rn(p1.z, dn);
        f[7] = 0.f;
        int w = tid >> 5;
        int off = (w > 0 ? n0 : 0) + (w > 1 ? n1 : 0) + (w > 2 ? n2 : 0);
        permS[off + __popc(bal & ((1u << (tid & 31)) - 1u))] = tid;
    }
    for(int i = tid; i < 448; i += 256) A1tS[i] = g_A1t[i];
    if(tid < 64)  c1S[tid] = g_c1[tid];
    if(tid < 128) c2S[tid] = g_c2[tid];
    __syncthreads();

    // phase 3: layer 1 for occupied slots -> bf16 hi/lo planes
    for(int i = tid; i < M*32; i += 256){
        int slot = i >> 5, jp = (i & 31)*2;
        int v = permS[slot];
        float s0 = c1S[jp], s1 = c1S[jp+1];
        const float* f = featS + v*8;
        #pragma unroll
        for(int k = 0; k < 7; k++){
            float fv = f[k];
            s0 = fmaf(fv, A1tS[k*64 + jp],   s0);
            s1 = fmaf(fv, A1tS[k*64 + jp+1], s1);
        }
        float h0 = fmaxf(s0, 0.f), h1 = fmaxf(s1, 0.f);
        __nv_bfloat16 h0h = __float2bfloat16(h0);
        __nv_bfloat16 h1h = __float2bfloat16(h1);
        __nv_bfloat16 h0l = __float2bfloat16(h0 - __bfloat162float(h0h));
        __nv_bfloat16 h1l = __float2bfloat16(h1 - __bfloat162float(h1h));
        uint32_t hiw = (uint32_t)*(uint16_t*)&h0h | ((uint32_t)*(uint16_t*)&h1h << 16);
        uint32_t low = (uint32_t)*(uint16_t*)&h0l | ((uint32_t)*(uint16_t*)&h1l << 16);
        *(uint32_t*)(Hhi + slot*PSTR + jp) = hiw;
        *(uint32_t*)(Hlo + slot*PSTR + jp) = low;
    }
    cpasync_wait0();
    __syncthreads();

    // phase 4: HMMA jobs. job j: chunk=j>>1 (16 slots), channel half=(j&1)*64.
    int nchunk = (M + 15) >> 4;
    int njobs = nchunk*2;
    int w = tid >> 5, lane = tid & 31;
    int g = lane >> 2, t = lane & 3;

    float accr[2][8][4];
    #pragma unroll
    for(int jj = 0; jj < 2; jj++)
        #pragma unroll
        for(int nt = 0; nt < 8; nt++)
            #pragma unroll
            for(int r = 0; r < 4; r++) accr[jj][nt][r] = 0.f;

    #pragma unroll
    for(int jj = 0; jj < 2; jj++){
        int j = w + jj*8;
        if(j < njobs){
            int chunk = j >> 1, cb = (j & 1)*64;
            int m0 = chunk*16;
            const __nv_bfloat16* hArow = Hhi + (m0+g)*PSTR;
            const __nv_bfloat16* hBrow = Hhi + (m0+g+8)*PSTR;
            const __nv_bfloat16* lArow = Hlo + (m0+g)*PSTR;
            const __nv_bfloat16* lBrow = Hlo + (m0+g+8)*PSTR;
            #pragma unroll
            for(int ks = 0; ks < 4; ks++){
                int kc = ks*16 + 2*t;
                uint32_t ah0 = *(const uint32_t*)(hArow + kc);
                uint32_t ah1 = *(const uint32_t*)(hBrow + kc);
                uint32_t ah2 = *(const uint32_t*)(hArow + kc + 8);
                uint32_t ah3 = *(const uint32_t*)(hBrow + kc + 8);
                uint32_t al0 = *(const uint32_t*)(lArow + kc);
                uint32_t al1 = *(const uint32_t*)(lBrow + kc);
                uint32_t al2 = *(const uint32_t*)(lArow + kc + 8);
                uint32_t al3 = *(const uint32_t*)(lBrow + kc + 8);
                #pragma unroll
                for(int nt = 0; nt < 8; nt++){
                    uint4 wf = Wfs[(cb + nt*8 + g)*20 + ks*4 + t];
                    mma_bf16(accr[jj][nt][0], accr[jj][nt][1], accr[jj][nt][2], accr[jj][nt][3],
                             ah0, ah1, ah2, ah3, wf.x, wf.y);
                    mma_bf16(accr[jj][nt][0], accr[jj][nt][1], accr[jj][nt][2], accr[jj][nt][3],
                             al0, al1, al2, al3, wf.x, wf.y);
                    mma_bf16(accr[jj][nt][0], accr[jj][nt][1], accr[jj][nt][2], accr[jj][nt][3],
                             ah0, ah1, ah2, ah3, wf.z, wf.w);
                }
            }
        }
    }
    unsigned qmask = (unsigned)auxS[12];
    __syncthreads();               // Wf + H dead from here (perm/aux outside 64KB overlay)

    // phase 5: masked zero, scatter, masked store
    for(int i = tid; i < 4096; i += 256){
        int c = i >> 5, vq = i & 31;
        if((qmask >> vq) & 1u)
            *(float4*)(oS + c*128 + ((vq ^ ((c >> 3) & 15)) << 2)) = z4;
    }
    __syncthreads();

    #pragma unroll
    for(int jj = 0; jj < 2; jj++){
        int j = w + jj*8;
        if(j < njobs){
            int chunk = j >> 1, cb = (j & 1)*64;
            int slotA = chunk*16 + g;
            int slotB = slotA + 8;
            int vA = (slotA < M) ? permS[slotA] : -1;
            int vB = (slotB < M) ? permS[slotB] : -1;
            #pragma unroll
            for(int nt = 0; nt < 8; nt++){
                int ch = cb + nt*8 + 2*t;
                int sw = (ch >> 3) & 15;
                float b0 = c2S[ch], b1 = c2S[ch+1];
                if(vA >= 0){
                    int idx = (((vA >> 2) ^ sw) << 2) + (vA & 3);
                    oS[ch*128 + idx]     = fmaxf(accr[jj][nt][0] + b0, 0.f);
                    oS[(ch+1)*128 + idx] = fmaxf(accr[jj][nt][1] + b1, 0.f);
                }
                if(vB >= 0){
                    int idx = (((vB >> 2) ^ sw) << 2) + (vB & 3);
                    oS[ch*128 + idx]     = fmaxf(accr[jj][nt][2] + b0, 0.f);
                    oS[(ch+1)*128 + idx] = fmaxf(accr[jj][nt][3] + b1, 0.f);
                }
            }
        }
    }
    __syncthreads();

    for(int i = tid; i < 4096; i += 256){
        int c = i >> 5, vq = i & 31;
        float4 v = ((qmask >> vq) & 1u)
            ? *(const float4*)(oS + c*128 + ((vq ^ ((c >> 3) & 15)) << 2)) : z4;
        __stcs((float4*)(ob + (size_t)c*G3) + vq, v);
    }
}

// ---------------- launch ----------------
extern "C" void kernel_launch(void* const* d_in, const int* in_sizes, int n_in,
                              void* d_out, int out_size){
    const float* pc  = (const float*)d_in[0];
    const float* W1  = (const float*)d_in[1];
    const float* b1  = (const float*)d_in[2];
    const float* g1  = (const float*)d_in[3];
    const float* be1 = (const float*)d_in[4];
    const float* rm1 = (const float*)d_in[5];
    const float* rv1 = (const float*)d_in[6];
    const float* W2  = (const float*)d_in[7];
    const float* b2  = (const float*)d_in[8];
    const float* g2  = (const float*)d_in[9];
    const float* be2 = (const float*)d_in[10];
    const float* rm2 = (const float*)d_in[11];
    const float* rv2 = (const float*)d_in[12];

    cudaFuncSetAttribute(k_tile, cudaFuncAttributeMaxDynamicSharedMemorySize, SB_BYTES);

    k_prep<<<2305, 256>>>(W1,b1,g1,be1,rm1,rv1,W2,b2,g2,be2,rm2,rv2, pc);
    k_voxel<<<dim3(782,4), 256>>>(pc);
    k_tile<<<NTILES, 256, SB_BYTES>>>((float*)d_out);
}